// round 5
// baseline (speedup 1.0000x reference)
#include <cuda_runtime.h>
#include <math.h>

// ---------------- problem constants ----------------
#define B_   8
#define T_   1024
#define C_   768
#define H_   12
#define E_   8
#define HS_  64
#define F_   3072
#define N_   (B_*T_)            // 8192 tokens
#define LN_EPS 1e-5f
#define ATT_SCALE 0.03608439182435161f   // 768^-0.5

// ---------------- scratch (static device memory; no allocations) ----------------
__device__ float g_h  [N_*C_];
__device__ float g_q  [H_*N_*HS_];
__device__ float g_k  [H_*N_*HS_];
__device__ float g_v  [H_*N_*HS_];
__device__ float g_o  [N_*C_];
__device__ float g_x1 [N_*C_];
__device__ float g_h2 [N_*C_];
__device__ int   g_cnt[E_];
__device__ int   g_tok[E_*N_];
__device__ int   g_texp [N_*2];
__device__ int   g_tslot[N_*2];
__device__ float g_tgate[N_*2];
__device__ float g_a1[(size_t)E_*N_*F_];   // per-expert hidden (cap 8192 rows each)
__device__ float g_a2[(size_t)2 *N_*F_];   // deep second hidden
__device__ float g_y [(size_t)E_*N_*C_];   // per-expert pre-LN output

// ---------------- helpers ----------------
__device__ __forceinline__ float gelu_f(float x) {
    return 0.5f * x * (1.0f + erff(x * 0.7071067811865476f));
}

__device__ __forceinline__ float block_reduce_sum(float v, float* red) {
    int tid = threadIdx.x;
    red[tid] = v; __syncthreads();
    #pragma unroll
    for (int o = 128; o > 0; o >>= 1) {
        if (tid < o) red[tid] += red[tid + o];
        __syncthreads();
    }
    float r = red[0];
    __syncthreads();
    return r;
}

// ---------------- LayerNorm over rows of 768, block=256 ----------------
__global__ void ln_kernel(const float* __restrict__ in, const float* __restrict__ g,
                          const float* __restrict__ b, float* __restrict__ out) {
    __shared__ float red[256];
    int row = blockIdx.x, tid = threadIdx.x;
    const float* x = in + (size_t)row * C_;
    float v0 = x[tid], v1 = x[tid + 256], v2 = x[tid + 512];
    float mean = block_reduce_sum(v0 + v1 + v2, red) * (1.0f / C_);
    float d0 = v0 - mean, d1 = v1 - mean, d2 = v2 - mean;
    float var = block_reduce_sum(d0*d0 + d1*d1 + d2*d2, red) * (1.0f / C_);
    float rs = 1.0f / sqrtf(var + LN_EPS);
    float* y = out + (size_t)row * C_;
    y[tid]       = d0 * rs * g[tid]       + b[tid];
    y[tid + 256] = d1 * rs * g[tid + 256] + b[tid + 256];
    y[tid + 512] = d2 * rs * g[tid + 512] + b[tid + 512];
}

// ---------------- generic SGEMM ----------------
// C[M,N] = A[M,K] @ B[K,N] (+bias) (EPI: 0 plain, 1 gelu, 2 +residual)
// Optional row gather on A; optional dynamic M via Mptr. grid.z offsets B and C
// by bzs/czs (used to batch the 12 attention heads into one launch).
template<int BM, int BN, int BK, int TM, int TN, int EPI>
__global__ void sgemm_k(const float* __restrict__ A, int lda,
                        const int* __restrict__ gather,
                        const float* __restrict__ Bm, int ldb, size_t bzs,
                        const float* __restrict__ bias,
                        const float* __restrict__ res,
                        float* __restrict__ Cm, int ldc, size_t czs,
                        int M, const int* __restrict__ Mp, int N, int K) {
    constexpr int THREADS = (BM/TM) * (BN/TN);
    if (Mp) M = *Mp;
    int m0 = blockIdx.y * BM;
    if (m0 >= M) return;
    int n0 = blockIdx.x * BN;
    Bm += (size_t)blockIdx.z * bzs;
    Cm += (size_t)blockIdx.z * czs;

    __shared__ float As[BK][BM + 4];
    __shared__ float Bs[BK][BN];
    __shared__ int   ridx[BM];

    int tid = threadIdx.x;
    for (int i = tid; i < BM; i += THREADS) {
        int r = m0 + i;
        ridx[i] = (r < M) ? (gather ? gather[r] : r) : -1;
    }
    __syncthreads();

    int tx = tid % (BN/TN), ty = tid / (BN/TN);
    float acc[TM][TN] = {};
    constexpr int LA4 = (BM*BK) / (THREADS*4);
    constexpr int LB4 = (BK*BN) / (THREADS*4);

    for (int k0 = 0; k0 < K; k0 += BK) {
        #pragma unroll
        for (int i = 0; i < LA4; i++) {
            int idx = (tid + i*THREADS) * 4;
            int ar = idx / BK, ac = idx % BK;
            int gr = ridx[ar];
            float4 v = make_float4(0.f, 0.f, 0.f, 0.f);
            if (gr >= 0) v = *(const float4*)(A + (size_t)gr*lda + k0 + ac);
            As[ac+0][ar] = v.x; As[ac+1][ar] = v.y;
            As[ac+2][ar] = v.z; As[ac+3][ar] = v.w;
        }
        #pragma unroll
        for (int i = 0; i < LB4; i++) {
            int idx = (tid + i*THREADS) * 4;
            int br = idx / BN, bc = idx % BN;
            *(float4*)&Bs[br][bc] = *(const float4*)(Bm + (size_t)(k0+br)*ldb + n0 + bc);
        }
        __syncthreads();
        #pragma unroll
        for (int kk = 0; kk < BK; kk++) {
            float ra[TM], rb[TN];
            #pragma unroll
            for (int i = 0; i < TM; i++) ra[i] = As[kk][ty*TM + i];
            #pragma unroll
            for (int j = 0; j < TN; j++) rb[j] = Bs[kk][tx*TN + j];
            #pragma unroll
            for (int i = 0; i < TM; i++)
                #pragma unroll
                for (int j = 0; j < TN; j++)
                    acc[i][j] += ra[i] * rb[j];
        }
        __syncthreads();
    }
    #pragma unroll
    for (int i = 0; i < TM; i++) {
        int r = m0 + ty*TM + i;
        if (r >= M) continue;
        #pragma unroll
        for (int j = 0; j < TN; j++) {
            int c = n0 + tx*TN + j;
            if (c >= N) continue;
            float v = acc[i][j];
            if (bias) v += bias[c];
            if (EPI == 1) v = gelu_f(v);
            if (EPI == 2) v += res[(size_t)r*ldc + c];
            Cm[(size_t)r*ldc + c] = v;
        }
    }
}

// ---------------- flash attention (fp32, causal, BQ=64, BKV=32, D=64) ----------------
__global__ void flash_kernel(const float* __restrict__ Q, const float* __restrict__ Kg,
                             const float* __restrict__ Vg, float* __restrict__ O) {
    constexpr int BQ = 64, BKV = 32;
    int qi = blockIdx.x;            // query tile 0..15
    int bh = blockIdx.y;            // 0..95
    int b = bh / H_, h = bh % H_;
    const float* Qb = Q  + ((size_t)h*N_ + (size_t)b*T_) * HS_;
    const float* Kb = Kg + ((size_t)h*N_ + (size_t)b*T_) * HS_;
    const float* Vb = Vg + ((size_t)h*N_ + (size_t)b*T_) * HS_;

    __shared__ float Qs[BQ][HS_+4];
    __shared__ float Ks[BKV][HS_+4];
    __shared__ float Vs[BKV][HS_+4];
    __shared__ float Ps[BQ][BKV+4];
    __shared__ float mrow[BQ], lrow[BQ];
    __shared__ float redm[BQ][4], reds[BQ][4];

    int tid = threadIdx.x;
    for (int i = tid; i < BQ*HS_/4; i += 256) {
        int idx = i * 4; int r = idx / HS_, c = idx % HS_;
        float4 v = *(const float4*)(Qb + (size_t)(qi*BQ + r)*HS_ + c);
        Qs[r][c+0] = v.x * ATT_SCALE; Qs[r][c+1] = v.y * ATT_SCALE;
        Qs[r][c+2] = v.z * ATT_SCALE; Qs[r][c+3] = v.w * ATT_SCALE;
    }
    if (tid < BQ) { mrow[tid] = -INFINITY; lrow[tid] = 0.f; }

    int r = tid / 4, cg = tid % 4;
    int rg = qi*BQ + r;
    float Oacc[16];
    #pragma unroll
    for (int i = 0; i < 16; i++) Oacc[i] = 0.f;

    int jmax = 2*qi + 1;
    for (int j = 0; j <= jmax; j++) {
        __syncthreads();   // tiles + stats safe to overwrite / first-use
        for (int i = tid; i < BKV*HS_/4; i += 256) {
            int idx = i * 4; int rr = idx / HS_, c = idx % HS_;
            float4 kv = *(const float4*)(Kb + (size_t)(j*BKV + rr)*HS_ + c);
            Ks[rr][c+0] = kv.x; Ks[rr][c+1] = kv.y; Ks[rr][c+2] = kv.z; Ks[rr][c+3] = kv.w;
            float4 vv = *(const float4*)(Vb + (size_t)(j*BKV + rr)*HS_ + c);
            Vs[rr][c+0] = vv.x; Vs[rr][c+1] = vv.y; Vs[rr][c+2] = vv.z; Vs[rr][c+3] = vv.w;
        }
        __syncthreads();

        float s[8];
        #pragma unroll
        for (int i = 0; i < 8; i++) s[i] = 0.f;
        #pragma unroll
        for (int d0 = 0; d0 < HS_; d0 += 16) {
            float qreg[16];
            #pragma unroll
            for (int d = 0; d < 16; d++) qreg[d] = Qs[r][d0+d];
            #pragma unroll
            for (int i = 0; i < 8; i++) {
                int c = cg*8 + i;
                #pragma unroll
                for (int d = 0; d < 16; d++)
                    s[i] += qreg[d] * Ks[c][d0+d];
            }
        }
        float lm = -INFINITY;
        #pragma unroll
        for (int i = 0; i < 8; i++) {
            int cgl = j*BKV + cg*8 + i;
            if (cgl > rg) s[i] = -INFINITY;
            lm = fmaxf(lm, s[i]);
        }
        redm[r][cg] = lm;
        __syncthreads();
        float mprev = mrow[r];
        float mnew = fmaxf(fmaxf(redm[r][0], redm[r][1]), fmaxf(redm[r][2], redm[r][3]));
        mnew = fmaxf(mprev, mnew);
        float ls = 0.f;
        #pragma unroll
        for (int i = 0; i < 8; i++) {
            float p = expf(s[i] - mnew);
            Ps[r][cg*8 + i] = p;
            ls += p;
        }
        reds[r][cg] = ls;
        float alpha = expf(mprev - mnew);
        __syncthreads();
        if (cg == 0) {
            float totl = reds[r][0] + reds[r][1] + reds[r][2] + reds[r][3];
            lrow[r] = lrow[r] * alpha + totl;
            mrow[r] = mnew;
        }
        #pragma unroll
        for (int d = 0; d < 16; d++) Oacc[d] *= alpha;
        #pragma unroll
        for (int c = 0; c < BKV; c++) {
            float p = Ps[r][c];
            #pragma unroll
            for (int d = 0; d < 16; d++)
                Oacc[d] += p * Vs[c][cg*16 + d];
        }
    }
    __syncthreads();
    float inv = 1.0f / lrow[r];
    float* orow = O + (size_t)(b*T_ + qi*BQ + r) * C_ + h*HS_ + cg*16;
    #pragma unroll
    for (int d = 0; d < 16; d++) orow[d] = Oacc[d] * inv;
}

// ---------------- reset router counters ----------------
__global__ void zero_cnt_kernel() {
    if (threadIdx.x < E_) g_cnt[threadIdx.x] = 0;
}

// ---------------- noisy top-2 router; builds per-expert token lists ----------------
__global__ void router_kernel(const float* __restrict__ h2,
                              const float* __restrict__ w_route, const float* __restrict__ b_route,
                              const float* __restrict__ w_noise, const float* __restrict__ b_noise,
                              const float* __restrict__ temp_p, const float* __restrict__ rnoise) {
    int n = blockIdx.x, tid = threadIdx.x;
    __shared__ float hrow[C_];
    __shared__ float sums[16];
    for (int i = tid; i < C_; i += 256) hrow[i] = h2[(size_t)n*C_ + i];
    __syncthreads();
    int w = tid / 32, lane = tid % 32;   // 8 warps: warp w -> route col w & noise col w
    float sr = 0.f, sn = 0.f;
    for (int c = lane; c < C_; c += 32) {
        float hv = hrow[c];
        sr += hv * w_route[c*E_ + w];
        sn += hv * w_noise[c*E_ + w];
    }
    #pragma unroll
    for (int o = 16; o > 0; o >>= 1) {
        sr += __shfl_down_sync(0xffffffffu, sr, o);
        sn += __shfl_down_sync(0xffffffffu, sn, o);
    }
    if (lane == 0) { sums[w] = sr; sums[8 + w] = sn; }
    __syncthreads();
    if (tid == 0) {
        float temp = fminf(fmaxf(temp_p[0], 0.5f), 2.0f);
        float noisy[E_];
        #pragma unroll
        for (int e = 0; e < E_; e++) {
            float logit = sums[e] + b_route[e];
            float z = sums[8 + e] + b_noise[e];
            float sp = (z > 20.f) ? z : log1pf(expf(z));
            noisy[e] = logit + temp * rnoise[(size_t)n*E_ + e] * sp;
        }
        int i0 = 0; float v0 = noisy[0];
        #pragma unroll
        for (int e = 1; e < E_; e++) if (noisy[e] > v0) { v0 = noisy[e]; i0 = e; }
        int i1 = -1; float v1 = -INFINITY;
        #pragma unroll
        for (int e = 0; e < E_; e++) if (e != i0 && noisy[e] > v1) { v1 = noisy[e]; i1 = e; }
        float eb = expf(v1 - v0);
        float gg0 = 1.0f / (1.0f + eb);
        float gg1 = eb / (1.0f + eb);
        int s0 = atomicAdd(&g_cnt[i0], 1);
        int s1 = atomicAdd(&g_cnt[i1], 1);
        g_tok[i0*N_ + s0] = n;  g_tok[i1*N_ + s1] = n;
        g_texp [n*2] = i0;      g_texp [n*2+1] = i1;
        g_tslot[n*2] = s0;      g_tslot[n*2+1] = s1;
        g_tgate[n*2] = gg0;     g_tgate[n*2+1] = gg1;
    }
}

// ---------------- final: per-token expert residual-LN + gated combine ----------------
__global__ void final_kernel(const float* __restrict__ x1, const float* __restrict__ h2,
                             const float* __restrict__ dlg, const float* __restrict__ dlb,
                             const float* __restrict__ slg, const float* __restrict__ slb,
                             float* __restrict__ out) {
    __shared__ float red[256];
    int n = blockIdx.x, tid = threadIdx.x;
    const float* hr = h2 + (size_t)n*C_;
    float h0 = hr[tid], h1 = hr[tid+256], h2v = hr[tid+512];
    float a0 = 0.f, a1 = 0.f, a2 = 0.f;
    for (int jj = 0; jj < 2; jj++) {
        int e = g_texp[n*2 + jj];
        int s = g_tslot[n*2 + jj];
        float gt = g_tgate[n*2 + jj];
        const float* y = g_y + ((size_t)e*N_ + s) * C_;
        float z0 = h0 + y[tid], z1 = h1 + y[tid+256], z2 = h2v + y[tid+512];
        float mean = block_reduce_sum(z0 + z1 + z2, red) * (1.0f / C_);
        float d0 = z0 - mean, d1 = z1 - mean, d2 = z2 - mean;
        float var = block_reduce_sum(d0*d0 + d1*d1 + d2*d2, red) * (1.0f / C_);
        float rs = 1.0f / sqrtf(var + LN_EPS);
        const float* gam; const float* bet;
        if (e < 2) { gam = dlg + e*C_;       bet = dlb + e*C_; }
        else       { gam = slg + (e-2)*C_;   bet = slb + (e-2)*C_; }
        a0 += gt * (d0*rs*gam[tid]     + bet[tid]);
        a1 += gt * (d1*rs*gam[tid+256] + bet[tid+256]);
        a2 += gt * (d2*rs*gam[tid+512] + bet[tid+512]);
    }
    const float* xr = x1 + (size_t)n*C_;
    float* orow = out + (size_t)n*C_;
    orow[tid]     = xr[tid]     + a0;
    orow[tid+256] = xr[tid+256] + a1;
    orow[tid+512] = xr[tid+512] + a2;
}

// ---------------- host ----------------
extern "C" void kernel_launch(void* const* d_in, const int* in_sizes, int n_in,
                              void* d_out, int out_size) {
    const float* x          = (const float*)d_in[0];
    const float* rnoise     = (const float*)d_in[1];
    const float* wq         = (const float*)d_in[2];
    const float* wk         = (const float*)d_in[3];
    const float* wv         = (const float*)d_in[4];
    const float* w_proj     = (const float*)d_in[5];
    const float* b_proj     = (const float*)d_in[6];
    const float* ln1_g      = (const float*)d_in[7];
    const float* ln1_b      = (const float*)d_in[8];
    const float* ln2_g      = (const float*)d_in[9];
    const float* ln2_b      = (const float*)d_in[10];
    const float* w_route    = (const float*)d_in[11];
    const float* b_route    = (const float*)d_in[12];
    const float* w_noise    = (const float*)d_in[13];
    const float* b_noise    = (const float*)d_in[14];
    const float* temp       = (const float*)d_in[15];
    const float* deep_w1    = (const float*)d_in[16];
    const float* deep_b1    = (const float*)d_in[17];
    const float* deep_w2    = (const float*)d_in[18];
    const float* deep_b2    = (const float*)d_in[19];
    const float* deep_w3    = (const float*)d_in[20];
    const float* deep_b3    = (const float*)d_in[21];
    const float* deep_ln_g  = (const float*)d_in[22];
    const float* deep_ln_b  = (const float*)d_in[23];
    const float* simple_w1  = (const float*)d_in[24];
    const float* simple_b1  = (const float*)d_in[25];
    const float* simple_w2  = (const float*)d_in[26];
    const float* simple_b2  = (const float*)d_in[27];
    const float* simple_ln_g= (const float*)d_in[28];
    const float* simple_ln_b= (const float*)d_in[29];
    float* out = (float*)d_out;

    float *ph, *pq, *pk, *pv, *po, *px1, *ph2, *pa1, *pa2, *py;
    int *pcnt, *ptok;
    cudaGetSymbolAddress((void**)&ph,  g_h);
    cudaGetSymbolAddress((void**)&pq,  g_q);
    cudaGetSymbolAddress((void**)&pk,  g_k);
    cudaGetSymbolAddress((void**)&pv,  g_v);
    cudaGetSymbolAddress((void**)&po,  g_o);
    cudaGetSymbolAddress((void**)&px1, g_x1);
    cudaGetSymbolAddress((void**)&ph2, g_h2);
    cudaGetSymbolAddress((void**)&pa1, g_a1);
    cudaGetSymbolAddress((void**)&pa2, g_a2);
    cudaGetSymbolAddress((void**)&py,  g_y);
    cudaGetSymbolAddress((void**)&pcnt, g_cnt);
    cudaGetSymbolAddress((void**)&ptok, g_tok);

    // 1) LN1
    ln_kernel<<<N_, 256>>>(x, ln1_g, ln1_b, ph);

    // 2) QKV: one launch per tensor, grid.z = heads
    {
        dim3 grid(1, N_/128, H_);
        sgemm_k<128,64,16,8,4,0><<<grid, 256>>>(ph, C_, nullptr,
            wq, HS_, (size_t)C_*HS_, nullptr, nullptr,
            pq, HS_, (size_t)N_*HS_, N_, nullptr, HS_, C_);
        sgemm_k<128,64,16,8,4,0><<<grid, 256>>>(ph, C_, nullptr,
            wk, HS_, (size_t)C_*HS_, nullptr, nullptr,
            pk, HS_, (size_t)N_*HS_, N_, nullptr, HS_, C_);
        sgemm_k<128,64,16,8,4,0><<<grid, 256>>>(ph, C_, nullptr,
            wv, HS_, (size_t)C_*HS_, nullptr, nullptr,
            pv, HS_, (size_t)N_*HS_, N_, nullptr, HS_, C_);
    }

    // 3) causal flash attention
    flash_kernel<<<dim3(T_/64, B_*H_), 256>>>(pq, pk, pv, po);

    // 4) out proj + residual (x1 = x + o@Wp + bp)
    sgemm_k<128,128,16,8,8,2><<<dim3(C_/128, N_/128), 256>>>(po, C_, nullptr,
        w_proj, C_, 0, b_proj, x, px1, C_, 0, N_, nullptr, C_, C_);

    // 5) LN2
    ln_kernel<<<N_, 256>>>(px1, ln2_g, ln2_b, ph2);

    // 6) router
    zero_cnt_kernel<<<1, 32>>>();
    router_kernel<<<N_, 256>>>(ph2, w_route, b_route, w_noise, b_noise, temp, rnoise);

    // 7) expert first layer (gathered rows), GELU epilogue
    for (int e = 0; e < E_; e++) {
        const float* W1 = (e < 2) ? deep_w1 + (size_t)e*C_*F_ : simple_w1 + (size_t)(e-2)*C_*F_;
        const float* B1 = (e < 2) ? deep_b1 + (size_t)e*F_    : simple_b1 + (size_t)(e-2)*F_;
        sgemm_k<128,128,16,8,8,1><<<dim3(F_/128, N_/128), 256>>>(
            ph2, C_, ptok + (size_t)e*N_, W1, F_, 0, B1, nullptr,
            pa1 + (size_t)e*N_*F_, F_, 0, N_, pcnt + e, F_, C_);
    }
    // 8) deep second layer, GELU
    for (int e = 0; e < 2; e++) {
        sgemm_k<128,128,16,8,8,1><<<dim3(F_/128, N_/128), 256>>>(
            pa1 + (size_t)e*N_*F_, F_, nullptr, deep_w2 + (size_t)e*F_*F_, F_, 0,
            deep_b2 + (size_t)e*F_, nullptr,
            pa2 + (size_t)e*N_*F_, F_, 0, N_, pcnt + e, F_, F_);
    }
    // 9) expert output layer -> y
    for (int e = 0; e < E_; e++) {
        const float *W, *Bb, *Ain;
        if (e < 2) { W = deep_w3 + (size_t)e*F_*C_;       Bb = deep_b3 + (size_t)e*C_;
                     Ain = pa2 + (size_t)e*N_*F_; }
        else       { W = simple_w2 + (size_t)(e-2)*F_*C_; Bb = simple_b2 + (size_t)(e-2)*C_;
                     Ain = pa1 + (size_t)e*N_*F_; }
        sgemm_k<128,128,16,8,8,0><<<dim3(C_/128, N_/128), 256>>>(
            Ain, F_, nullptr, W, C_, 0, Bb, nullptr,
            py + (size_t)e*N_*C_, C_, 0, N_, pcnt + e, C_, F_);
    }

    // 10) per-token gated residual-LN combine
    final_kernel<<<N_, 256>>>(px1, ph2, deep_ln_g, deep_ln_b, simple_ln_g, simple_ln_b, out);
}

// round 6
// speedup vs baseline: 1.5356x; 1.5356x over previous
#include <cuda_runtime.h>
#include <math.h>
#include <stdint.h>

// ---------------- problem constants ----------------
#define B_   8
#define T_   1024
#define C_   768
#define H_   12
#define E_   8
#define HS_  64
#define F_   3072
#define N_   (B_*T_)            // 8192 tokens
#define LN_EPS 1e-5f
#define ATT_SCALE 0.03608439182435161f   // 768^-0.5

// ---------------- scratch (static device memory; no allocations) ----------------
__device__ float g_h  [N_*C_];
__device__ float g_q  [H_*N_*HS_];
__device__ float g_k  [H_*N_*HS_];
__device__ float g_v  [H_*N_*HS_];
__device__ float g_o  [N_*C_];
__device__ float g_x1 [N_*C_];
__device__ float g_h2 [N_*C_];
__device__ int   g_cnt[E_];
__device__ int   g_tok[E_*N_];
__device__ int   g_texp [N_*2];
__device__ int   g_tslot[N_*2];
__device__ float g_tgate[N_*2];
__device__ float g_a1[(size_t)E_*N_*F_];   // per-expert hidden (cap 8192 rows each)
__device__ float g_a2[(size_t)2 *N_*F_];   // deep second hidden
__device__ float g_y [(size_t)E_*N_*C_];   // per-expert pre-LN output

// ---------------- helpers ----------------
__device__ __forceinline__ float gelu_f(float x) {
    return 0.5f * x * (1.0f + erff(x * 0.7071067811865476f));
}

__device__ __forceinline__ float tf32r(float x) {
    uint32_t u; asm("cvt.rna.tf32.f32 %0, %1;" : "=r"(u) : "f"(x));
    return __uint_as_float(u);
}

__device__ __forceinline__ void mma_tf32(float* c, const uint32_t* a, const uint32_t* b) {
    asm volatile("mma.sync.aligned.m16n8k8.row.col.f32.tf32.tf32.f32 "
        "{%0,%1,%2,%3}, {%4,%5,%6,%7}, {%8,%9}, {%0,%1,%2,%3};"
        : "+f"(c[0]), "+f"(c[1]), "+f"(c[2]), "+f"(c[3])
        : "r"(a[0]), "r"(a[1]), "r"(a[2]), "r"(a[3]), "r"(b[0]), "r"(b[1]));
}

__device__ __forceinline__ float block_reduce_sum(float v, float* red) {
    int tid = threadIdx.x;
    red[tid] = v; __syncthreads();
    #pragma unroll
    for (int o = 128; o > 0; o >>= 1) {
        if (tid < o) red[tid] += red[tid + o];
        __syncthreads();
    }
    float r = red[0];
    __syncthreads();
    return r;
}

// ---------------- LayerNorm over rows of 768, block=256 ----------------
__global__ void ln_kernel(const float* __restrict__ in, const float* __restrict__ g,
                          const float* __restrict__ b, float* __restrict__ out) {
    __shared__ float red[256];
    int row = blockIdx.x, tid = threadIdx.x;
    const float* x = in + (size_t)row * C_;
    float v0 = x[tid], v1 = x[tid + 256], v2 = x[tid + 512];
    float mean = block_reduce_sum(v0 + v1 + v2, red) * (1.0f / C_);
    float d0 = v0 - mean, d1 = v1 - mean, d2 = v2 - mean;
    float var = block_reduce_sum(d0*d0 + d1*d1 + d2*d2, red) * (1.0f / C_);
    float rs = 1.0f / sqrtf(var + LN_EPS);
    float* y = out + (size_t)row * C_;
    y[tid]       = d0 * rs * g[tid]       + b[tid];
    y[tid + 256] = d1 * rs * g[tid + 256] + b[tid + 256];
    y[tid + 512] = d2 * rs * g[tid + 512] + b[tid + 512];
}

// ---------------- generic fp32 SGEMM (attention path only) ----------------
template<int BM, int BN, int BK, int TM, int TN, int EPI>
__global__ void sgemm_k(const float* __restrict__ A, int lda,
                        const int* __restrict__ gather,
                        const float* __restrict__ Bm, int ldb, size_t bzs,
                        const float* __restrict__ bias,
                        const float* __restrict__ res,
                        float* __restrict__ Cm, int ldc, size_t czs,
                        int M, const int* __restrict__ Mp, int N, int K) {
    constexpr int THREADS = (BM/TM) * (BN/TN);
    if (Mp) M = *Mp;
    int m0 = blockIdx.y * BM;
    if (m0 >= M) return;
    int n0 = blockIdx.x * BN;
    Bm += (size_t)blockIdx.z * bzs;
    Cm += (size_t)blockIdx.z * czs;

    __shared__ float As[BK][BM + 4];
    __shared__ float Bs[BK][BN];
    __shared__ int   ridx[BM];

    int tid = threadIdx.x;
    for (int i = tid; i < BM; i += THREADS) {
        int r = m0 + i;
        ridx[i] = (r < M) ? (gather ? gather[r] : r) : -1;
    }
    __syncthreads();

    int tx = tid % (BN/TN), ty = tid / (BN/TN);
    float acc[TM][TN] = {};
    constexpr int LA4 = (BM*BK) / (THREADS*4);
    constexpr int LB4 = (BK*BN) / (THREADS*4);

    for (int k0 = 0; k0 < K; k0 += BK) {
        #pragma unroll
        for (int i = 0; i < LA4; i++) {
            int idx = (tid + i*THREADS) * 4;
            int ar = idx / BK, ac = idx % BK;
            int gr = ridx[ar];
            float4 v = make_float4(0.f, 0.f, 0.f, 0.f);
            if (gr >= 0) v = *(const float4*)(A + (size_t)gr*lda + k0 + ac);
            As[ac+0][ar] = v.x; As[ac+1][ar] = v.y;
            As[ac+2][ar] = v.z; As[ac+3][ar] = v.w;
        }
        #pragma unroll
        for (int i = 0; i < LB4; i++) {
            int idx = (tid + i*THREADS) * 4;
            int br = idx / BN, bc = idx % BN;
            *(float4*)&Bs[br][bc] = *(const float4*)(Bm + (size_t)(k0+br)*ldb + n0 + bc);
        }
        __syncthreads();
        #pragma unroll
        for (int kk = 0; kk < BK; kk++) {
            float ra[TM], rb[TN];
            #pragma unroll
            for (int i = 0; i < TM; i++) ra[i] = As[kk][ty*TM + i];
            #pragma unroll
            for (int j = 0; j < TN; j++) rb[j] = Bs[kk][tx*TN + j];
            #pragma unroll
            for (int i = 0; i < TM; i++)
                #pragma unroll
                for (int j = 0; j < TN; j++)
                    acc[i][j] += ra[i] * rb[j];
        }
        __syncthreads();
    }
    #pragma unroll
    for (int i = 0; i < TM; i++) {
        int r = m0 + ty*TM + i;
        if (r >= M) continue;
        #pragma unroll
        for (int j = 0; j < TN; j++) {
            int c = n0 + tx*TN + j;
            if (c >= N) continue;
            float v = acc[i][j];
            if (bias) v += bias[c];
            if (EPI == 1) v = gelu_f(v);
            if (EPI == 2) v += res[(size_t)r*ldc + c];
            Cm[(size_t)r*ldc + c] = v;
        }
    }
}

// ---------------- tf32 tensor-core GEMM (expert path) ----------------
// C[M,N] = A[M,K] @ B[K,N] + bias, EPI: 0 plain, 1 gelu.
// Dynamic M via Mp (early-exit), optional row gather on A.
// 128x128x32 CTA tile, 8 warps of 64x32, mma.sync.m16n8k8.tf32.
template<int EPI>
__global__ void __launch_bounds__(256, 2)
tf32_gemm(const float* __restrict__ A, int lda,
          const int* __restrict__ gather,
          const float* __restrict__ Bm, int ldb,
          const float* __restrict__ bias,
          float* __restrict__ Cm, int ldc,
          const int* __restrict__ Mp, int N, int K) {
    constexpr int BM = 128, BN = 128, BK = 32;
    constexpr int LDA_S = BK + 4;    // 36 floats: bank = (4*row + k) % 32 -> conflict-free frags
    constexpr int LDB_S = BN + 4;    // 132 floats: bank = (4*k + n) % 32 -> conflict-free frags
    const int M = *Mp;
    int m0 = blockIdx.y * BM;
    if (m0 >= M) return;
    int n0 = blockIdx.x * BN;

    __shared__ float As[BM][LDA_S];
    __shared__ float Bs[BK][LDB_S];
    __shared__ int   ridx[BM];

    int tid = threadIdx.x;
    int lane = tid & 31, wid = tid >> 5;
    int wm = (wid & 1) * 64;       // warp m offset within CTA tile
    int wn = (wid >> 1) * 32;      // warp n offset
    int lr = lane >> 2;            // 0..7
    int lc = lane & 3;             // 0..3

    for (int i = tid; i < BM; i += 256) {
        int r = m0 + i;
        ridx[i] = (r < M) ? (gather ? gather[r] : r) : -1;
    }
    __syncthreads();

    float acc[4][4][4];
    #pragma unroll
    for (int mt = 0; mt < 4; mt++)
        #pragma unroll
        for (int nt = 0; nt < 4; nt++)
            #pragma unroll
            for (int i = 0; i < 4; i++) acc[mt][nt][i] = 0.f;

    for (int k0 = 0; k0 < K; k0 += BK) {
        // A tile: 128 rows x 32 floats = 1024 float4, 4 per thread
        #pragma unroll
        for (int i = 0; i < 4; i++) {
            int idx = tid + i*256;
            int row = idx >> 3, c4 = (idx & 7) * 4;
            int gr = ridx[row];
            float4 v = make_float4(0.f,0.f,0.f,0.f);
            if (gr >= 0) v = *(const float4*)(A + (size_t)gr*lda + k0 + c4);
            As[row][c4+0] = tf32r(v.x); As[row][c4+1] = tf32r(v.y);
            As[row][c4+2] = tf32r(v.z); As[row][c4+3] = tf32r(v.w);
        }
        // B tile: 32 rows x 128 floats = 1024 float4
        #pragma unroll
        for (int i = 0; i < 4; i++) {
            int idx = tid + i*256;
            int kr = idx >> 5, c4 = (idx & 31) * 4;
            float4 v = *(const float4*)(Bm + (size_t)(k0+kr)*ldb + n0 + c4);
            Bs[kr][c4+0] = tf32r(v.x); Bs[kr][c4+1] = tf32r(v.y);
            Bs[kr][c4+2] = tf32r(v.z); Bs[kr][c4+3] = tf32r(v.w);
        }
        __syncthreads();
        #pragma unroll
        for (int k8 = 0; k8 < 4; k8++) {
            uint32_t a[4][4], b[4][2];
            #pragma unroll
            for (int mt = 0; mt < 4; mt++) {
                int rb = wm + mt*16;
                a[mt][0] = __float_as_uint(As[rb + lr    ][k8*8 + lc    ]);
                a[mt][1] = __float_as_uint(As[rb + 8 + lr][k8*8 + lc    ]);
                a[mt][2] = __float_as_uint(As[rb + lr    ][k8*8 + 4 + lc]);
                a[mt][3] = __float_as_uint(As[rb + 8 + lr][k8*8 + 4 + lc]);
            }
            #pragma unroll
            for (int nt = 0; nt < 4; nt++) {
                b[nt][0] = __float_as_uint(Bs[k8*8 + lc    ][wn + nt*8 + lr]);
                b[nt][1] = __float_as_uint(Bs[k8*8 + 4 + lc][wn + nt*8 + lr]);
            }
            #pragma unroll
            for (int mt = 0; mt < 4; mt++)
                #pragma unroll
                for (int nt = 0; nt < 4; nt++)
                    mma_tf32(acc[mt][nt], a[mt], b[nt]);
        }
        __syncthreads();
    }

    // epilogue: bias (+gelu), float2 stores
    #pragma unroll
    for (int mt = 0; mt < 4; mt++) {
        int r0 = m0 + wm + mt*16 + lr;
        int r1 = r0 + 8;
        #pragma unroll
        for (int nt = 0; nt < 4; nt++) {
            int c = n0 + wn + nt*8 + lc*2;
            float bz0 = bias[c], bz1 = bias[c+1];
            float v0 = acc[mt][nt][0] + bz0, v1 = acc[mt][nt][1] + bz1;
            float v2 = acc[mt][nt][2] + bz0, v3 = acc[mt][nt][3] + bz1;
            if (EPI == 1) { v0 = gelu_f(v0); v1 = gelu_f(v1); v2 = gelu_f(v2); v3 = gelu_f(v3); }
            if (r0 < M) *(float2*)(Cm + (size_t)r0*ldc + c) = make_float2(v0, v1);
            if (r1 < M) *(float2*)(Cm + (size_t)r1*ldc + c) = make_float2(v2, v3);
        }
    }
}

// ---------------- flash attention (fp32, causal, BQ=64, BKV=32, D=64) ----------------
__global__ void flash_kernel(const float* __restrict__ Q, const float* __restrict__ Kg,
                             const float* __restrict__ Vg, float* __restrict__ O) {
    constexpr int BQ = 64, BKV = 32;
    int qi = blockIdx.x;            // query tile 0..15
    int bh = blockIdx.y;            // 0..95
    int b = bh / H_, h = bh % H_;
    const float* Qb = Q  + ((size_t)h*N_ + (size_t)b*T_) * HS_;
    const float* Kb = Kg + ((size_t)h*N_ + (size_t)b*T_) * HS_;
    const float* Vb = Vg + ((size_t)h*N_ + (size_t)b*T_) * HS_;

    __shared__ float Qs[BQ][HS_+4];
    __shared__ float Ks[BKV][HS_+4];
    __shared__ float Vs[BKV][HS_+4];
    __shared__ float Ps[BQ][BKV+4];
    __shared__ float mrow[BQ], lrow[BQ];
    __shared__ float redm[BQ][4], reds[BQ][4];

    int tid = threadIdx.x;
    for (int i = tid; i < BQ*HS_/4; i += 256) {
        int idx = i * 4; int r = idx / HS_, c = idx % HS_;
        float4 v = *(const float4*)(Qb + (size_t)(qi*BQ + r)*HS_ + c);
        Qs[r][c+0] = v.x * ATT_SCALE; Qs[r][c+1] = v.y * ATT_SCALE;
        Qs[r][c+2] = v.z * ATT_SCALE; Qs[r][c+3] = v.w * ATT_SCALE;
    }
    if (tid < BQ) { mrow[tid] = -INFINITY; lrow[tid] = 0.f; }

    int r = tid / 4, cg = tid % 4;
    int rg = qi*BQ + r;
    float Oacc[16];
    #pragma unroll
    for (int i = 0; i < 16; i++) Oacc[i] = 0.f;

    int jmax = 2*qi + 1;
    for (int j = 0; j <= jmax; j++) {
        __syncthreads();
        for (int i = tid; i < BKV*HS_/4; i += 256) {
            int idx = i * 4; int rr = idx / HS_, c = idx % HS_;
            float4 kv = *(const float4*)(Kb + (size_t)(j*BKV + rr)*HS_ + c);
            Ks[rr][c+0] = kv.x; Ks[rr][c+1] = kv.y; Ks[rr][c+2] = kv.z; Ks[rr][c+3] = kv.w;
            float4 vv = *(const float4*)(Vb + (size_t)(j*BKV + rr)*HS_ + c);
            Vs[rr][c+0] = vv.x; Vs[rr][c+1] = vv.y; Vs[rr][c+2] = vv.z; Vs[rr][c+3] = vv.w;
        }
        __syncthreads();

        float s[8];
        #pragma unroll
        for (int i = 0; i < 8; i++) s[i] = 0.f;
        #pragma unroll
        for (int d0 = 0; d0 < HS_; d0 += 16) {
            float qreg[16];
            #pragma unroll
            for (int d = 0; d < 16; d++) qreg[d] = Qs[r][d0+d];
            #pragma unroll
            for (int i = 0; i < 8; i++) {
                int c = cg*8 + i;
                #pragma unroll
                for (int d = 0; d < 16; d++)
                    s[i] += qreg[d] * Ks[c][d0+d];
            }
        }
        float lm = -INFINITY;
        #pragma unroll
        for (int i = 0; i < 8; i++) {
            int cgl = j*BKV + cg*8 + i;
            if (cgl > rg) s[i] = -INFINITY;
            lm = fmaxf(lm, s[i]);
        }
        redm[r][cg] = lm;
        __syncthreads();
        float mprev = mrow[r];
        float mnew = fmaxf(fmaxf(redm[r][0], redm[r][1]), fmaxf(redm[r][2], redm[r][3]));
        mnew = fmaxf(mprev, mnew);
        float ls = 0.f;
        #pragma unroll
        for (int i = 0; i < 8; i++) {
            float p = expf(s[i] - mnew);
            Ps[r][cg*8 + i] = p;
            ls += p;
        }
        reds[r][cg] = ls;
        float alpha = expf(mprev - mnew);
        __syncthreads();
        if (cg == 0) {
            float totl = reds[r][0] + reds[r][1] + reds[r][2] + reds[r][3];
            lrow[r] = lrow[r] * alpha + totl;
            mrow[r] = mnew;
        }
        #pragma unroll
        for (int d = 0; d < 16; d++) Oacc[d] *= alpha;
        #pragma unroll
        for (int c = 0; c < BKV; c++) {
            float p = Ps[r][c];
            #pragma unroll
            for (int d = 0; d < 16; d++)
                Oacc[d] += p * Vs[c][cg*16 + d];
        }
    }
    __syncthreads();
    float inv = 1.0f / lrow[r];
    float* orow = O + (size_t)(b*T_ + qi*BQ + r) * C_ + h*HS_ + cg*16;
    #pragma unroll
    for (int d = 0; d < 16; d++) orow[d] = Oacc[d] * inv;
}

// ---------------- reset router counters ----------------
__global__ void zero_cnt_kernel() {
    if (threadIdx.x < E_) g_cnt[threadIdx.x] = 0;
}

// ---------------- noisy top-2 router; builds per-expert token lists ----------------
__global__ void router_kernel(const float* __restrict__ h2,
                              const float* __restrict__ w_route, const float* __restrict__ b_route,
                              const float* __restrict__ w_noise, const float* __restrict__ b_noise,
                              const float* __restrict__ temp_p, const float* __restrict__ rnoise) {
    int n = blockIdx.x, tid = threadIdx.x;
    __shared__ float hrow[C_];
    __shared__ float sums[16];
    for (int i = tid; i < C_; i += 256) hrow[i] = h2[(size_t)n*C_ + i];
    __syncthreads();
    int w = tid / 32, lane = tid % 32;
    float sr = 0.f, sn = 0.f;
    for (int c = lane; c < C_; c += 32) {
        float hv = hrow[c];
        sr += hv * w_route[c*E_ + w];
        sn += hv * w_noise[c*E_ + w];
    }
    #pragma unroll
    for (int o = 16; o > 0; o >>= 1) {
        sr += __shfl_down_sync(0xffffffffu, sr, o);
        sn += __shfl_down_sync(0xffffffffu, sn, o);
    }
    if (lane == 0) { sums[w] = sr; sums[8 + w] = sn; }
    __syncthreads();
    if (tid == 0) {
        float temp = fminf(fmaxf(temp_p[0], 0.5f), 2.0f);
        float noisy[E_];
        #pragma unroll
        for (int e = 0; e < E_; e++) {
            float logit = sums[e] + b_route[e];
            float z = sums[8 + e] + b_noise[e];
            float sp = (z > 20.f) ? z : log1pf(expf(z));
            noisy[e] = logit + temp * rnoise[(size_t)n*E_ + e] * sp;
        }
        int i0 = 0; float v0 = noisy[0];
        #pragma unroll
        for (int e = 1; e < E_; e++) if (noisy[e] > v0) { v0 = noisy[e]; i0 = e; }
        int i1 = -1; float v1 = -INFINITY;
        #pragma unroll
        for (int e = 0; e < E_; e++) if (e != i0 && noisy[e] > v1) { v1 = noisy[e]; i1 = e; }
        float eb = expf(v1 - v0);
        float gg0 = 1.0f / (1.0f + eb);
        float gg1 = eb / (1.0f + eb);
        int s0 = atomicAdd(&g_cnt[i0], 1);
        int s1 = atomicAdd(&g_cnt[i1], 1);
        g_tok[i0*N_ + s0] = n;  g_tok[i1*N_ + s1] = n;
        g_texp [n*2] = i0;      g_texp [n*2+1] = i1;
        g_tslot[n*2] = s0;      g_tslot[n*2+1] = s1;
        g_tgate[n*2] = gg0;     g_tgate[n*2+1] = gg1;
    }
}

// ---------------- final: per-token expert residual-LN + gated combine ----------------
__global__ void final_kernel(const float* __restrict__ x1, const float* __restrict__ h2,
                             const float* __restrict__ dlg, const float* __restrict__ dlb,
                             const float* __restrict__ slg, const float* __restrict__ slb,
                             float* __restrict__ out) {
    __shared__ float red[256];
    int n = blockIdx.x, tid = threadIdx.x;
    const float* hr = h2 + (size_t)n*C_;
    float h0 = hr[tid], h1 = hr[tid+256], h2v = hr[tid+512];
    float a0 = 0.f, a1 = 0.f, a2 = 0.f;
    for (int jj = 0; jj < 2; jj++) {
        int e = g_texp[n*2 + jj];
        int s = g_tslot[n*2 + jj];
        float gt = g_tgate[n*2 + jj];
        const float* y = g_y + ((size_t)e*N_ + s) * C_;
        float z0 = h0 + y[tid], z1 = h1 + y[tid+256], z2 = h2v + y[tid+512];
        float mean = block_reduce_sum(z0 + z1 + z2, red) * (1.0f / C_);
        float d0 = z0 - mean, d1 = z1 - mean, d2 = z2 - mean;
        float var = block_reduce_sum(d0*d0 + d1*d1 + d2*d2, red) * (1.0f / C_);
        float rs = 1.0f / sqrtf(var + LN_EPS);
        const float* gam; const float* bet;
        if (e < 2) { gam = dlg + e*C_;       bet = dlb + e*C_; }
        else       { gam = slg + (e-2)*C_;   bet = slb + (e-2)*C_; }
        a0 += gt * (d0*rs*gam[tid]     + bet[tid]);
        a1 += gt * (d1*rs*gam[tid+256] + bet[tid+256]);
        a2 += gt * (d2*rs*gam[tid+512] + bet[tid+512]);
    }
    const float* xr = x1 + (size_t)n*C_;
    float* orow = out + (size_t)n*C_;
    orow[tid]     = xr[tid]     + a0;
    orow[tid+256] = xr[tid+256] + a1;
    orow[tid+512] = xr[tid+512] + a2;
}

// ---------------- host ----------------
extern "C" void kernel_launch(void* const* d_in, const int* in_sizes, int n_in,
                              void* d_out, int out_size) {
    const float* x          = (const float*)d_in[0];
    const float* rnoise     = (const float*)d_in[1];
    const float* wq         = (const float*)d_in[2];
    const float* wk         = (const float*)d_in[3];
    const float* wv         = (const float*)d_in[4];
    const float* w_proj     = (const float*)d_in[5];
    const float* b_proj     = (const float*)d_in[6];
    const float* ln1_g      = (const float*)d_in[7];
    const float* ln1_b      = (const float*)d_in[8];
    const float* ln2_g      = (const float*)d_in[9];
    const float* ln2_b      = (const float*)d_in[10];
    const float* w_route    = (const float*)d_in[11];
    const float* b_route    = (const float*)d_in[12];
    const float* w_noise    = (const float*)d_in[13];
    const float* b_noise    = (const float*)d_in[14];
    const float* temp       = (const float*)d_in[15];
    const float* deep_w1    = (const float*)d_in[16];
    const float* deep_b1    = (const float*)d_in[17];
    const float* deep_w2    = (const float*)d_in[18];
    const float* deep_b2    = (const float*)d_in[19];
    const float* deep_w3    = (const float*)d_in[20];
    const float* deep_b3    = (const float*)d_in[21];
    const float* deep_ln_g  = (const float*)d_in[22];
    const float* deep_ln_b  = (const float*)d_in[23];
    const float* simple_w1  = (const float*)d_in[24];
    const float* simple_b1  = (const float*)d_in[25];
    const float* simple_w2  = (const float*)d_in[26];
    const float* simple_b2  = (const float*)d_in[27];
    const float* simple_ln_g= (const float*)d_in[28];
    const float* simple_ln_b= (const float*)d_in[29];
    float* out = (float*)d_out;

    float *ph, *pq, *pk, *pv, *po, *px1, *ph2, *pa1, *pa2, *py;
    int *pcnt, *ptok;
    cudaGetSymbolAddress((void**)&ph,  g_h);
    cudaGetSymbolAddress((void**)&pq,  g_q);
    cudaGetSymbolAddress((void**)&pk,  g_k);
    cudaGetSymbolAddress((void**)&pv,  g_v);
    cudaGetSymbolAddress((void**)&po,  g_o);
    cudaGetSymbolAddress((void**)&px1, g_x1);
    cudaGetSymbolAddress((void**)&ph2, g_h2);
    cudaGetSymbolAddress((void**)&pa1, g_a1);
    cudaGetSymbolAddress((void**)&pa2, g_a2);
    cudaGetSymbolAddress((void**)&py,  g_y);
    cudaGetSymbolAddress((void**)&pcnt, g_cnt);
    cudaGetSymbolAddress((void**)&ptok, g_tok);

    // 1) LN1
    ln_kernel<<<N_, 256>>>(x, ln1_g, ln1_b, ph);

    // 2) QKV (fp32 — feeds router path, keep exact)
    {
        dim3 grid(1, N_/128, H_);
        sgemm_k<128,64,16,8,4,0><<<grid, 256>>>(ph, C_, nullptr,
            wq, HS_, (size_t)C_*HS_, nullptr, nullptr,
            pq, HS_, (size_t)N_*HS_, N_, nullptr, HS_, C_);
        sgemm_k<128,64,16,8,4,0><<<grid, 256>>>(ph, C_, nullptr,
            wk, HS_, (size_t)C_*HS_, nullptr, nullptr,
            pk, HS_, (size_t)N_*HS_, N_, nullptr, HS_, C_);
        sgemm_k<128,64,16,8,4,0><<<grid, 256>>>(ph, C_, nullptr,
            wv, HS_, (size_t)C_*HS_, nullptr, nullptr,
            pv, HS_, (size_t)N_*HS_, N_, nullptr, HS_, C_);
    }

    // 3) causal flash attention (fp32)
    flash_kernel<<<dim3(T_/64, B_*H_), 256>>>(pq, pk, pv, po);

    // 4) out proj + residual (fp32 — feeds router path)
    sgemm_k<128,128,16,8,8,2><<<dim3(C_/128, N_/128), 256>>>(po, C_, nullptr,
        w_proj, C_, 0, b_proj, x, px1, C_, 0, N_, nullptr, C_, C_);

    // 5) LN2
    ln_kernel<<<N_, 256>>>(px1, ln2_g, ln2_b, ph2);

    // 6) router (fp32)
    zero_cnt_kernel<<<1, 32>>>();
    router_kernel<<<N_, 256>>>(ph2, w_route, b_route, w_noise, b_noise, temp, rnoise);

    // 7) expert first layer (gathered rows), GELU epilogue — tf32 tensor cores
    for (int e = 0; e < E_; e++) {
        const float* W1 = (e < 2) ? deep_w1 + (size_t)e*C_*F_ : simple_w1 + (size_t)(e-2)*C_*F_;
        const float* B1 = (e < 2) ? deep_b1 + (size_t)e*F_    : simple_b1 + (size_t)(e-2)*F_;
        tf32_gemm<1><<<dim3(F_/128, N_/128), 256>>>(
            ph2, C_, ptok + (size_t)e*N_, W1, F_, B1,
            pa1 + (size_t)e*N_*F_, F_, pcnt + e, F_, C_);
    }
    // 8) deep second layer, GELU — tf32
    for (int e = 0; e < 2; e++) {
        tf32_gemm<1><<<dim3(F_/128, N_/128), 256>>>(
            pa1 + (size_t)e*N_*F_, F_, nullptr, deep_w2 + (size_t)e*F_*F_, F_,
            deep_b2 + (size_t)e*F_,
            pa2 + (size_t)e*N_*F_, F_, pcnt + e, F_, F_);
    }
    // 9) expert output layer -> y — tf32
    for (int e = 0; e < E_; e++) {
        const float *W, *Bb, *Ain;
        if (e < 2) { W = deep_w3 + (size_t)e*F_*C_;       Bb = deep_b3 + (size_t)e*C_;
                     Ain = pa2 + (size_t)e*N_*F_; }
        else       { W = simple_w2 + (size_t)(e-2)*F_*C_; Bb = simple_b2 + (size_t)(e-2)*C_;
                     Ain = pa1 + (size_t)e*N_*F_; }
        tf32_gemm<0><<<dim3(C_/128, N_/128), 256>>>(
            Ain, F_, nullptr, W, C_, Bb,
            py + (size_t)e*N_*C_, C_, pcnt + e, C_, F_);
    }

    // 10) per-token gated residual-LN combine
    final_kernel<<<N_, 256>>>(px1, ph2, deep_ln_g, deep_ln_b, simple_ln_g, simple_ln_b, out);
}

// round 10
// speedup vs baseline: 2.2854x; 1.4883x over previous
#include <cuda_runtime.h>
#include <math.h>
#include <stdint.h>

// ---------------- problem constants ----------------
#define B_   8
#define T_   1024
#define C_   768
#define H_   12
#define E_   8
#define HS_  64
#define F_   3072
#define N_   (B_*T_)            // 8192 tokens
#define LN_EPS 1e-5f
#define ATT_SCALE 0.03608439182435161f   // 768^-0.5

// ---------------- scratch (static device memory; no allocations) ----------------
__device__ float g_h  [N_*C_];
__device__ float g_q  [H_*N_*HS_];
__device__ float g_k  [H_*N_*HS_];
__device__ float g_v  [H_*N_*HS_];
__device__ float g_o  [N_*C_];
__device__ float g_x1 [N_*C_];
__device__ float g_h2 [N_*C_];
__device__ int   g_cnt[E_];
__device__ int   g_tok[E_*N_];
__device__ int   g_texp [N_*2];
__device__ int   g_tslot[N_*2];
__device__ float g_tgate[N_*2];
__device__ float g_a1[(size_t)E_*N_*F_];   // per-expert hidden
__device__ float g_a2[(size_t)2 *N_*F_];   // deep second hidden
__device__ float g_y [(size_t)E_*N_*C_];   // per-expert pre-LN output

// ---------------- helpers ----------------
__device__ __forceinline__ float gelu_f(float x) {
    return 0.5f * x * (1.0f + erff(x * 0.7071067811865476f));
}

__device__ __forceinline__ void mma_tf32(float* c, const uint32_t* a, const uint32_t* b) {
    asm volatile("mma.sync.aligned.m16n8k8.row.col.f32.tf32.tf32.f32 "
        "{%0,%1,%2,%3}, {%4,%5,%6,%7}, {%8,%9}, {%0,%1,%2,%3};"
        : "+f"(c[0]), "+f"(c[1]), "+f"(c[2]), "+f"(c[3])
        : "r"(a[0]), "r"(a[1]), "r"(a[2]), "r"(a[3]), "r"(b[0]), "r"(b[1]));
}

__device__ __forceinline__ float block_reduce_sum(float v, float* red) {
    int tid = threadIdx.x;
    red[tid] = v; __syncthreads();
    #pragma unroll
    for (int o = 128; o > 0; o >>= 1) {
        if (tid < o) red[tid] += red[tid + o];
        __syncthreads();
    }
    float r = red[0];
    __syncthreads();
    return r;
}

// ---------------- LayerNorm over rows of 768, block=256 ----------------
__global__ void ln_kernel(const float* __restrict__ in, const float* __restrict__ g,
                          const float* __restrict__ b, float* __restrict__ out) {
    __shared__ float red[256];
    int row = blockIdx.x, tid = threadIdx.x;
    const float* x = in + (size_t)row * C_;
    float v0 = x[tid], v1 = x[tid + 256], v2 = x[tid + 512];
    float mean = block_reduce_sum(v0 + v1 + v2, red) * (1.0f / C_);
    float d0 = v0 - mean, d1 = v1 - mean, d2 = v2 - mean;
    float var = block_reduce_sum(d0*d0 + d1*d1 + d2*d2, red) * (1.0f / C_);
    float rs = 1.0f / sqrtf(var + LN_EPS);
    float* y = out + (size_t)row * C_;
    y[tid]       = d0 * rs * g[tid]       + b[tid];
    y[tid + 256] = d1 * rs * g[tid + 256] + b[tid + 256];
    y[tid + 512] = d2 * rs * g[tid + 512] + b[tid + 512];
}

// ---------------- generic fp32 SGEMM (attention path only) ----------------
template<int BM, int BN, int BK, int TM, int TN, int EPI>
__global__ void sgemm_k(const float* __restrict__ A, int lda,
                        const int* __restrict__ gather,
                        const float* __restrict__ Bm, int ldb, size_t bzs,
                        const float* __restrict__ bias,
                        const float* __restrict__ res,
                        float* __restrict__ Cm, int ldc, size_t czs,
                        int M, const int* __restrict__ Mp, int N, int K) {
    constexpr int THREADS = (BM/TM) * (BN/TN);
    if (Mp) M = *Mp;
    int m0 = blockIdx.y * BM;
    if (m0 >= M) return;
    int n0 = blockIdx.x * BN;
    Bm += (size_t)blockIdx.z * bzs;
    Cm += (size_t)blockIdx.z * czs;

    __shared__ float As[BK][BM + 4];
    __shared__ float Bs[BK][BN];
    __shared__ int   ridx[BM];

    int tid = threadIdx.x;
    for (int i = tid; i < BM; i += THREADS) {
        int r = m0 + i;
        ridx[i] = (r < M) ? (gather ? gather[r] : r) : -1;
    }
    __syncthreads();

    int tx = tid % (BN/TN), ty = tid / (BN/TN);
    float acc[TM][TN] = {};
    constexpr int LA4 = (BM*BK) / (THREADS*4);
    constexpr int LB4 = (BK*BN) / (THREADS*4);

    for (int k0 = 0; k0 < K; k0 += BK) {
        #pragma unroll
        for (int i = 0; i < LA4; i++) {
            int idx = (tid + i*THREADS) * 4;
            int ar = idx / BK, ac = idx % BK;
            int gr = ridx[ar];
            float4 v = make_float4(0.f, 0.f, 0.f, 0.f);
            if (gr >= 0) v = *(const float4*)(A + (size_t)gr*lda + k0 + ac);
            As[ac+0][ar] = v.x; As[ac+1][ar] = v.y;
            As[ac+2][ar] = v.z; As[ac+3][ar] = v.w;
        }
        #pragma unroll
        for (int i = 0; i < LB4; i++) {
            int idx = (tid + i*THREADS) * 4;
            int br = idx / BN, bc = idx % BN;
            *(float4*)&Bs[br][bc] = *(const float4*)(Bm + (size_t)(k0+br)*ldb + n0 + bc);
        }
        __syncthreads();
        #pragma unroll
        for (int kk = 0; kk < BK; kk++) {
            float ra[TM], rb[TN];
            #pragma unroll
            for (int i = 0; i < TM; i++) ra[i] = As[kk][ty*TM + i];
            #pragma unroll
            for (int j = 0; j < TN; j++) rb[j] = Bs[kk][tx*TN + j];
            #pragma unroll
            for (int i = 0; i < TM; i++)
                #pragma unroll
                for (int j = 0; j < TN; j++)
                    acc[i][j] += ra[i] * rb[j];
        }
        __syncthreads();
    }
    #pragma unroll
    for (int i = 0; i < TM; i++) {
        int r = m0 + ty*TM + i;
        if (r >= M) continue;
        #pragma unroll
        for (int j = 0; j < TN; j++) {
            int c = n0 + tx*TN + j;
            if (c >= N) continue;
            float v = acc[i][j];
            if (bias) v += bias[c];
            if (EPI == 1) v = gelu_f(v);
            if (EPI == 2) v += res[(size_t)r*ldc + c];
            Cm[(size_t)r*ldc + c] = v;
        }
    }
}

// ---------------- tf32 tensor-core GEMM, 3-stage cp.async pipeline ----------------
// C[M,N] = A[M,K] @ B[K,N] + bias, EPI: 0 plain, 1 gelu.
// Dynamic M via Mp (early-exit), optional row gather on A.
// 128x128x32 CTA tile, 8 warps of 64x32, mma.sync.m16n8k8.tf32 (raw fp32 bits,
// HW-truncated mantissa). 3-stage cp.async.cg, one __syncthreads per iter.
#define LDA_S 36     // A smem row stride (floats): conflict-free frag loads
#define LDB_S 132    // B smem row stride
#define STG_F 8832   // floats per stage: 128*36 + 32*132
#define TF32_SMEM (3 * STG_F * 4)

__device__ __forceinline__ void cp_tile(uint32_t sb, const float* __restrict__ A, int lda,
                                        const int* __restrict__ ridx,
                                        const float* __restrict__ Bm, int ldb,
                                        int n0, int k0, int tid) {
    #pragma unroll
    for (int i = 0; i < 4; i++) {            // A: 128 rows x 32 floats = 1024 x 16B
        int idx = tid + i*256;
        int row = idx >> 3, c4 = (idx & 7) << 2;
        int gr = ridx[row];
        uint32_t dst = sb + (uint32_t)(row*LDA_S + c4) * 4u;
        const float* src = A + (size_t)(gr < 0 ? 0 : gr)*lda + k0 + c4;
        int sz = (gr >= 0) ? 16 : 0;
        asm volatile("cp.async.cg.shared.global [%0], [%1], 16, %2;"
                     :: "r"(dst), "l"(src), "r"(sz));
    }
    #pragma unroll
    for (int i = 0; i < 4; i++) {            // B: 32 rows x 128 floats = 1024 x 16B
        int idx = tid + i*256;
        int kr = idx >> 5, c4 = (idx & 31) << 2;
        uint32_t dst = sb + (uint32_t)(4608 + kr*LDB_S + c4) * 4u;
        const float* src = Bm + (size_t)(k0+kr)*ldb + n0 + c4;
        asm volatile("cp.async.cg.shared.global [%0], [%1], 16;"
                     :: "r"(dst), "l"(src));
    }
}

template<int EPI>
__global__ void __launch_bounds__(256, 2)
tf32_gemm(const float* __restrict__ A, int lda,
          const int* __restrict__ gather,
          const float* __restrict__ Bm, int ldb,
          const float* __restrict__ bias,
          float* __restrict__ Cm, int ldc,
          const int* __restrict__ Mp, int N, int K) {
    constexpr int BM = 128, BK = 32;
    extern __shared__ float dsm[];
    __shared__ int ridx[BM];

    const int M = *Mp;
    int m0 = blockIdx.y * BM;
    if (m0 >= M) return;
    int n0 = blockIdx.x * 128;

    int tid = threadIdx.x;
    int lane = tid & 31, wid = tid >> 5;
    int wm = (wid & 1) * 64;
    int wn = (wid >> 1) * 32;
    int lr = lane >> 2;
    int lc = lane & 3;

    for (int i = tid; i < BM; i += 256) {
        int r = m0 + i;
        ridx[i] = (r < M) ? (gather ? gather[r] : r) : -1;
    }
    __syncthreads();

    uint32_t sbase;
    { unsigned long long gp = __cvta_generic_to_shared(dsm); sbase = (uint32_t)gp; }

    const int iters = K / BK;
    // prologue: stages 0,1
    cp_tile(sbase + 0*STG_F*4, A, lda, ridx, Bm, ldb, n0, 0, tid);
    asm volatile("cp.async.commit_group;");
    if (iters > 1) cp_tile(sbase + 1*STG_F*4, A, lda, ridx, Bm, ldb, n0, BK, tid);
    asm volatile("cp.async.commit_group;");

    float acc[4][4][4];
    #pragma unroll
    for (int mt = 0; mt < 4; mt++)
        #pragma unroll
        for (int nt = 0; nt < 4; nt++)
            #pragma unroll
            for (int i = 0; i < 4; i++) acc[mt][nt][i] = 0.f;

    int st = 0;
    for (int it = 0; it < iters; it++) {
        asm volatile("cp.async.wait_group 1;");
        __syncthreads();
        // prefetch stage it+2
        if (it + 2 < iters) {
            int ps = (st + 2 >= 3) ? st - 1 : st + 2;
            cp_tile(sbase + (uint32_t)ps*STG_F*4, A, lda, ridx, Bm, ldb, n0, (it+2)*BK, tid);
        }
        asm volatile("cp.async.commit_group;");

        const float* As = dsm + (size_t)st * STG_F;
        const float* Bs = As + 4608;
        #pragma unroll
        for (int k8 = 0; k8 < 4; k8++) {
            uint32_t a[4][4], b[4][2];
            #pragma unroll
            for (int mt = 0; mt < 4; mt++) {
                int rb = wm + mt*16;
                a[mt][0] = __float_as_uint(As[(rb + lr    )*LDA_S + k8*8 + lc    ]);
                a[mt][1] = __float_as_uint(As[(rb + 8 + lr)*LDA_S + k8*8 + lc    ]);
                a[mt][2] = __float_as_uint(As[(rb + lr    )*LDA_S + k8*8 + 4 + lc]);
                a[mt][3] = __float_as_uint(As[(rb + 8 + lr)*LDA_S + k8*8 + 4 + lc]);
            }
            #pragma unroll
            for (int nt = 0; nt < 4; nt++) {
                b[nt][0] = __float_as_uint(Bs[(k8*8 + lc    )*LDB_S + wn + nt*8 + lr]);
                b[nt][1] = __float_as_uint(Bs[(k8*8 + 4 + lc)*LDB_S + wn + nt*8 + lr]);
            }
            #pragma unroll
            for (int mt = 0; mt < 4; mt++)
                #pragma unroll
                for (int nt = 0; nt < 4; nt++)
                    mma_tf32(acc[mt][nt], a[mt], b[nt]);
        }
        st = (st + 1 >= 3) ? 0 : st + 1;
    }

    // epilogue: bias (+gelu), float2 stores
    #pragma unroll
    for (int mt = 0; mt < 4; mt++) {
        int r0 = m0 + wm + mt*16 + lr;
        int r1 = r0 + 8;
        #pragma unroll
        for (int nt = 0; nt < 4; nt++) {
            int c = n0 + wn + nt*8 + lc*2;
            float bz0 = bias[c], bz1 = bias[c+1];
            float v0 = acc[mt][nt][0] + bz0, v1 = acc[mt][nt][1] + bz1;
            float v2 = acc[mt][nt][2] + bz0, v3 = acc[mt][nt][3] + bz1;
            if (EPI == 1) { v0 = gelu_f(v0); v1 = gelu_f(v1); v2 = gelu_f(v2); v3 = gelu_f(v3); }
            if (r0 < M) *(float2*)(Cm + (size_t)r0*ldc + c) = make_float2(v0, v1);
            if (r1 < M) *(float2*)(Cm + (size_t)r1*ldc + c) = make_float2(v2, v3);
        }
    }
}

// ---------------- flash attention (fp32, causal, BQ=64, BKV=32, D=64) ----------------
__global__ void flash_kernel(const float* __restrict__ Q, const float* __restrict__ Kg,
                             const float* __restrict__ Vg, float* __restrict__ O) {
    constexpr int BQ = 64, BKV = 32;
    int qi = blockIdx.x;
    int bh = blockIdx.y;
    int b = bh / H_, h = bh % H_;
    const float* Qb = Q  + ((size_t)h*N_ + (size_t)b*T_) * HS_;
    const float* Kb = Kg + ((size_t)h*N_ + (size_t)b*T_) * HS_;
    const float* Vb = Vg + ((size_t)h*N_ + (size_t)b*T_) * HS_;

    __shared__ float Qs[BQ][HS_+4];
    __shared__ float Ks[BKV][HS_+4];
    __shared__ float Vs[BKV][HS_+4];
    __shared__ float Ps[BQ][BKV+4];
    __shared__ float mrow[BQ], lrow[BQ];
    __shared__ float redm[BQ][4], reds[BQ][4];

    int tid = threadIdx.x;
    for (int i = tid; i < BQ*HS_/4; i += 256) {
        int idx = i * 4; int r = idx / HS_, c = idx % HS_;
        float4 v = *(const float4*)(Qb + (size_t)(qi*BQ + r)*HS_ + c);
        Qs[r][c+0] = v.x * ATT_SCALE; Qs[r][c+1] = v.y * ATT_SCALE;
        Qs[r][c+2] = v.z * ATT_SCALE; Qs[r][c+3] = v.w * ATT_SCALE;
    }
    if (tid < BQ) { mrow[tid] = -INFINITY; lrow[tid] = 0.f; }

    int r = tid / 4, cg = tid % 4;
    int rg = qi*BQ + r;
    float Oacc[16];
    #pragma unroll
    for (int i = 0; i < 16; i++) Oacc[i] = 0.f;

    int jmax = 2*qi + 1;
    for (int j = 0; j <= jmax; j++) {
        __syncthreads();
        for (int i = tid; i < BKV*HS_/4; i += 256) {
            int idx = i * 4; int rr = idx / HS_, c = idx % HS_;
            float4 kv = *(const float4*)(Kb + (size_t)(j*BKV + rr)*HS_ + c);
            Ks[rr][c+0] = kv.x; Ks[rr][c+1] = kv.y; Ks[rr][c+2] = kv.z; Ks[rr][c+3] = kv.w;
            float4 vv = *(const float4*)(Vb + (size_t)(j*BKV + rr)*HS_ + c);
            Vs[rr][c+0] = vv.x; Vs[rr][c+1] = vv.y; Vs[rr][c+2] = vv.z; Vs[rr][c+3] = vv.w;
        }
        __syncthreads();

        float s[8];
        #pragma unroll
        for (int i = 0; i < 8; i++) s[i] = 0.f;
        #pragma unroll
        for (int d0 = 0; d0 < HS_; d0 += 16) {
            float qreg[16];
            #pragma unroll
            for (int d = 0; d < 16; d++) qreg[d] = Qs[r][d0+d];
            #pragma unroll
            for (int i = 0; i < 8; i++) {
                int c = cg*8 + i;
                #pragma unroll
                for (int d = 0; d < 16; d++)
                    s[i] += qreg[d] * Ks[c][d0+d];
            }
        }
        float lm = -INFINITY;
        #pragma unroll
        for (int i = 0; i < 8; i++) {
            int cgl = j*BKV + cg*8 + i;
            if (cgl > rg) s[i] = -INFINITY;
            lm = fmaxf(lm, s[i]);
        }
        redm[r][cg] = lm;
        __syncthreads();
        float mprev = mrow[r];
        float mnew = fmaxf(fmaxf(redm[r][0], redm[r][1]), fmaxf(redm[r][2], redm[r][3]));
        mnew = fmaxf(mprev, mnew);
        float ls = 0.f;
        #pragma unroll
        for (int i = 0; i < 8; i++) {
            float p = expf(s[i] - mnew);
            Ps[r][cg*8 + i] = p;
            ls += p;
        }
        reds[r][cg] = ls;
        float alpha = expf(mprev - mnew);
        __syncthreads();
        if (cg == 0) {
            float totl = reds[r][0] + reds[r][1] + reds[r][2] + reds[r][3];
            lrow[r] = lrow[r] * alpha + totl;
            mrow[r] = mnew;
        }
        #pragma unroll
        for (int d = 0; d < 16; d++) Oacc[d] *= alpha;
        #pragma unroll
        for (int c = 0; c < BKV; c++) {
            float p = Ps[r][c];
            #pragma unroll
            for (int d = 0; d < 16; d++)
                Oacc[d] += p * Vs[c][cg*16 + d];
        }
    }
    __syncthreads();
    float inv = 1.0f / lrow[r];
    float* orow = O + (size_t)(b*T_ + qi*BQ + r) * C_ + h*HS_ + cg*16;
    #pragma unroll
    for (int d = 0; d < 16; d++) orow[d] = Oacc[d] * inv;
}

// ---------------- reset router counters ----------------
__global__ void zero_cnt_kernel() {
    if (threadIdx.x < E_) g_cnt[threadIdx.x] = 0;
}

// ---------------- noisy top-2 router; builds per-expert token lists ----------------
__global__ void router_kernel(const float* __restrict__ h2,
                              const float* __restrict__ w_route, const float* __restrict__ b_route,
                              const float* __restrict__ w_noise, const float* __restrict__ b_noise,
                              const float* __restrict__ temp_p, const float* __restrict__ rnoise) {
    int n = blockIdx.x, tid = threadIdx.x;
    __shared__ float hrow[C_];
    __shared__ float sums[16];
    for (int i = tid; i < C_; i += 256) hrow[i] = h2[(size_t)n*C_ + i];
    __syncthreads();
    int w = tid / 32, lane = tid % 32;
    float sr = 0.f, sn = 0.f;
    for (int c = lane; c < C_; c += 32) {
        float hv = hrow[c];
        sr += hv * w_route[c*E_ + w];
        sn += hv * w_noise[c*E_ + w];
    }
    #pragma unroll
    for (int o = 16; o > 0; o >>= 1) {
        sr += __shfl_down_sync(0xffffffffu, sr, o);
        sn += __shfl_down_sync(0xffffffffu, sn, o);
    }
    if (lane == 0) { sums[w] = sr; sums[8 + w] = sn; }
    __syncthreads();
    if (tid == 0) {
        float temp = fminf(fmaxf(temp_p[0], 0.5f), 2.0f);
        float noisy[E_];
        #pragma unroll
        for (int e = 0; e < E_; e++) {
            float logit = sums[e] + b_route[e];
            float z = sums[8 + e] + b_noise[e];
            float sp = (z > 20.f) ? z : log1pf(expf(z));
            noisy[e] = logit + temp * rnoise[(size_t)n*E_ + e] * sp;
        }
        int i0 = 0; float v0 = noisy[0];
        #pragma unroll
        for (int e = 1; e < E_; e++) if (noisy[e] > v0) { v0 = noisy[e]; i0 = e; }
        int i1 = -1; float v1 = -INFINITY;
        #pragma unroll
        for (int e = 0; e < E_; e++) if (e != i0 && noisy[e] > v1) { v1 = noisy[e]; i1 = e; }
        float eb = expf(v1 - v0);
        float gg0 = 1.0f / (1.0f + eb);
        float gg1 = eb / (1.0f + eb);
        int s0 = atomicAdd(&g_cnt[i0], 1);
        int s1 = atomicAdd(&g_cnt[i1], 1);
        g_tok[i0*N_ + s0] = n;  g_tok[i1*N_ + s1] = n;
        g_texp [n*2] = i0;      g_texp [n*2+1] = i1;
        g_tslot[n*2] = s0;      g_tslot[n*2+1] = s1;
        g_tgate[n*2] = gg0;     g_tgate[n*2+1] = gg1;
    }
}

// ---------------- final: per-token expert residual-LN + gated combine ----------------
__global__ void final_kernel(const float* __restrict__ x1, const float* __restrict__ h2,
                             const float* __restrict__ dlg, const float* __restrict__ dlb,
                             const float* __restrict__ slg, const float* __restrict__ slb,
                             float* __restrict__ out) {
    __shared__ float red[256];
    int n = blockIdx.x, tid = threadIdx.x;
    const float* hr = h2 + (size_t)n*C_;
    float h0 = hr[tid], h1 = hr[tid+256], h2v = hr[tid+512];
    float a0 = 0.f, a1 = 0.f, a2 = 0.f;
    for (int jj = 0; jj < 2; jj++) {
        int e = g_texp[n*2 + jj];
        int s = g_tslot[n*2 + jj];
        float gt = g_tgate[n*2 + jj];
        const float* y = g_y + ((size_t)e*N_ + s) * C_;
        float z0 = h0 + y[tid], z1 = h1 + y[tid+256], z2 = h2v + y[tid+512];
        float mean = block_reduce_sum(z0 + z1 + z2, red) * (1.0f / C_);
        float d0 = z0 - mean, d1 = z1 - mean, d2 = z2 - mean;
        float var = block_reduce_sum(d0*d0 + d1*d1 + d2*d2, red) * (1.0f / C_);
        float rs = 1.0f / sqrtf(var + LN_EPS);
        const float* gam; const float* bet;
        if (e < 2) { gam = dlg + e*C_;       bet = dlb + e*C_; }
        else       { gam = slg + (e-2)*C_;   bet = slb + (e-2)*C_; }
        a0 += gt * (d0*rs*gam[tid]     + bet[tid]);
        a1 += gt * (d1*rs*gam[tid+256] + bet[tid+256]);
        a2 += gt * (d2*rs*gam[tid+512] + bet[tid+512]);
    }
    const float* xr = x1 + (size_t)n*C_;
    float* orow = out + (size_t)n*C_;
    orow[tid]     = xr[tid]     + a0;
    orow[tid+256] = xr[tid+256] + a1;
    orow[tid+512] = xr[tid+512] + a2;
}

// ---------------- host ----------------
extern "C" void kernel_launch(void* const* d_in, const int* in_sizes, int n_in,
                              void* d_out, int out_size) {
    const float* x          = (const float*)d_in[0];
    const float* rnoise     = (const float*)d_in[1];
    const float* wq         = (const float*)d_in[2];
    const float* wk         = (const float*)d_in[3];
    const float* wv         = (const float*)d_in[4];
    const float* w_proj     = (const float*)d_in[5];
    const float* b_proj     = (const float*)d_in[6];
    const float* ln1_g      = (const float*)d_in[7];
    const float* ln1_b      = (const float*)d_in[8];
    const float* ln2_g      = (const float*)d_in[9];
    const float* ln2_b      = (const float*)d_in[10];
    const float* w_route    = (const float*)d_in[11];
    const float* b_route    = (const float*)d_in[12];
    const float* w_noise    = (const float*)d_in[13];
    const float* b_noise    = (const float*)d_in[14];
    const float* temp       = (const float*)d_in[15];
    const float* deep_w1    = (const float*)d_in[16];
    const float* deep_b1    = (const float*)d_in[17];
    const float* deep_w2    = (const float*)d_in[18];
    const float* deep_b2    = (const float*)d_in[19];
    const float* deep_w3    = (const float*)d_in[20];
    const float* deep_b3    = (const float*)d_in[21];
    const float* deep_ln_g  = (const float*)d_in[22];
    const float* deep_ln_b  = (const float*)d_in[23];
    const float* simple_w1  = (const float*)d_in[24];
    const float* simple_b1  = (const float*)d_in[25];
    const float* simple_w2  = (const float*)d_in[26];
    const float* simple_b2  = (const float*)d_in[27];
    const float* simple_ln_g= (const float*)d_in[28];
    const float* simple_ln_b= (const float*)d_in[29];
    float* out = (float*)d_out;

    float *ph, *pq, *pk, *pv, *po, *px1, *ph2, *pa1, *pa2, *py;
    int *pcnt, *ptok;
    cudaGetSymbolAddress((void**)&ph,  g_h);
    cudaGetSymbolAddress((void**)&pq,  g_q);
    cudaGetSymbolAddress((void**)&pk,  g_k);
    cudaGetSymbolAddress((void**)&pv,  g_v);
    cudaGetSymbolAddress((void**)&po,  g_o);
    cudaGetSymbolAddress((void**)&px1, g_x1);
    cudaGetSymbolAddress((void**)&ph2, g_h2);
    cudaGetSymbolAddress((void**)&pa1, g_a1);
    cudaGetSymbolAddress((void**)&pa2, g_a2);
    cudaGetSymbolAddress((void**)&py,  g_y);
    cudaGetSymbolAddress((void**)&pcnt, g_cnt);
    cudaGetSymbolAddress((void**)&ptok, g_tok);

    // opt-in to >48KB dynamic smem (host-side attribute set; not a stream op)
    cudaFuncSetAttribute(tf32_gemm<0>, cudaFuncAttributeMaxDynamicSharedMemorySize, TF32_SMEM);
    cudaFuncSetAttribute(tf32_gemm<1>, cudaFuncAttributeMaxDynamicSharedMemorySize, TF32_SMEM);

    // 1) LN1
    ln_kernel<<<N_, 256>>>(x, ln1_g, ln1_b, ph);

    // 2) QKV (fp32 — feeds router path, keep exact)
    {
        dim3 grid(1, N_/128, H_);
        sgemm_k<128,64,16,8,4,0><<<grid, 256>>>(ph, C_, nullptr,
            wq, HS_, (size_t)C_*HS_, nullptr, nullptr,
            pq, HS_, (size_t)N_*HS_, N_, nullptr, HS_, C_);
        sgemm_k<128,64,16,8,4,0><<<grid, 256>>>(ph, C_, nullptr,
            wk, HS_, (size_t)C_*HS_, nullptr, nullptr,
            pk, HS_, (size_t)N_*HS_, N_, nullptr, HS_, C_);
        sgemm_k<128,64,16,8,4,0><<<grid, 256>>>(ph, C_, nullptr,
            wv, HS_, (size_t)C_*HS_, nullptr, nullptr,
            pv, HS_, (size_t)N_*HS_, N_, nullptr, HS_, C_);
    }

    // 3) causal flash attention (fp32)
    flash_kernel<<<dim3(T_/64, B_*H_), 256>>>(pq, pk, pv, po);

    // 4) out proj + residual (fp32 — feeds router path)
    sgemm_k<128,128,16,8,8,2><<<dim3(C_/128, N_/128), 256>>>(po, C_, nullptr,
        w_proj, C_, 0, b_proj, x, px1, C_, 0, N_, nullptr, C_, C_);

    // 5) LN2
    ln_kernel<<<N_, 256>>>(px1, ln2_g, ln2_b, ph2);

    // 6) router (fp32)
    zero_cnt_kernel<<<1, 32>>>();
    router_kernel<<<N_, 256>>>(ph2, w_route, b_route, w_noise, b_noise, temp, rnoise);

    // 7) expert first layer (gathered rows), GELU epilogue — tf32 pipelined
    for (int e = 0; e < E_; e++) {
        const float* W1 = (e < 2) ? deep_w1 + (size_t)e*C_*F_ : simple_w1 + (size_t)(e-2)*C_*F_;
        const float* B1 = (e < 2) ? deep_b1 + (size_t)e*F_    : simple_b1 + (size_t)(e-2)*F_;
        tf32_gemm<1><<<dim3(F_/128, N_/128), 256, TF32_SMEM>>>(
            ph2, C_, ptok + (size_t)e*N_, W1, F_, B1,
            pa1 + (size_t)e*N_*F_, F_, pcnt + e, F_, C_);
    }
    // 8) deep second layer, GELU — tf32 pipelined
    for (int e = 0; e < 2; e++) {
        tf32_gemm<1><<<dim3(F_/128, N_/128), 256, TF32_SMEM>>>(
            pa1 + (size_t)e*N_*F_, F_, nullptr, deep_w2 + (size_t)e*F_*F_, F_,
            deep_b2 + (size_t)e*F_,
            pa2 + (size_t)e*N_*F_, F_, pcnt + e, F_, F_);
    }
    // 9) expert output layer -> y — tf32 pipelined
    for (int e = 0; e < E_; e++) {
        const float *W, *Bb, *Ain;
        if (e < 2) { W = deep_w3 + (size_t)e*F_*C_;       Bb = deep_b3 + (size_t)e*C_;
                     Ain = pa2 + (size_t)e*N_*F_; }
        else       { W = simple_w2 + (size_t)(e-2)*F_*C_; Bb = simple_b2 + (size_t)(e-2)*C_;
                     Ain = pa1 + (size_t)e*N_*F_; }
        tf32_gemm<0><<<dim3(C_/128, N_/128), 256, TF32_SMEM>>>(
            Ain, F_, nullptr, W, C_, Bb,
            py + (size_t)e*N_*C_, C_, pcnt + e, C_, F_);
    }

    // 10) per-token gated residual-LN combine
    final_kernel<<<N_, 256>>>(px1, ph2, deep_ln_g, deep_ln_b, simple_ln_g, simple_ln_b, out);
}

// round 11
// speedup vs baseline: 2.3373x; 1.0227x over previous
#include <cuda_runtime.h>
#include <math.h>
#include <stdint.h>

// ---------------- problem constants ----------------
#define B_   8
#define T_   1024
#define C_   768
#define H_   12
#define E_   8
#define HS_  64
#define F_   3072
#define N_   (B_*T_)            // 8192 tokens
#define LN_EPS 1e-5f
#define ATT_SCALE 0.03608439182435161f   // 768^-0.5

// ---------------- scratch (static device memory; no allocations) ----------------
__device__ float g_h  [N_*C_];
__device__ float g_q  [H_*N_*HS_];
__device__ float g_k  [H_*N_*HS_];
__device__ float g_v  [H_*N_*HS_];
__device__ float g_o  [N_*C_];
__device__ float g_x1 [N_*C_];
__device__ float g_h2 [N_*C_];
__device__ int   g_cnt[E_];
__device__ int   g_tok[E_*N_];
__device__ int   g_texp [N_*2];
__device__ int   g_tslot[N_*2];
__device__ float g_tgate[N_*2];
__device__ float g_a1[(size_t)E_*N_*F_];   // per-expert hidden
__device__ float g_a2[(size_t)2 *N_*F_];   // deep second hidden
__device__ float g_y [(size_t)E_*N_*C_];   // per-expert pre-LN output

// ---------------- helpers ----------------
__device__ __forceinline__ float gelu_f(float x) {
    return 0.5f * x * (1.0f + erff(x * 0.7071067811865476f));
}

__device__ __forceinline__ void mma_tf32(float* c, const uint32_t* a, const uint32_t* b) {
    asm volatile("mma.sync.aligned.m16n8k8.row.col.f32.tf32.tf32.f32 "
        "{%0,%1,%2,%3}, {%4,%5,%6,%7}, {%8,%9}, {%0,%1,%2,%3};"
        : "+f"(c[0]), "+f"(c[1]), "+f"(c[2]), "+f"(c[3])
        : "r"(a[0]), "r"(a[1]), "r"(a[2]), "r"(a[3]), "r"(b[0]), "r"(b[1]));
}

__device__ __forceinline__ void ldsm_x4(uint32_t* r, uint32_t addr) {
    asm volatile("ldmatrix.sync.aligned.m8n8.x4.shared.b16 {%0,%1,%2,%3}, [%4];"
        : "=r"(r[0]), "=r"(r[1]), "=r"(r[2]), "=r"(r[3]) : "r"(addr));
}

__device__ __forceinline__ float block_reduce_sum(float v, float* red) {
    int tid = threadIdx.x;
    red[tid] = v; __syncthreads();
    #pragma unroll
    for (int o = 128; o > 0; o >>= 1) {
        if (tid < o) red[tid] += red[tid + o];
        __syncthreads();
    }
    float r = red[0];
    __syncthreads();
    return r;
}

// ---------------- LayerNorm over rows of 768, block=256 ----------------
__global__ void ln_kernel(const float* __restrict__ in, const float* __restrict__ g,
                          const float* __restrict__ b, float* __restrict__ out) {
    __shared__ float red[256];
    int row = blockIdx.x, tid = threadIdx.x;
    const float* x = in + (size_t)row * C_;
    float v0 = x[tid], v1 = x[tid + 256], v2 = x[tid + 512];
    float mean = block_reduce_sum(v0 + v1 + v2, red) * (1.0f / C_);
    float d0 = v0 - mean, d1 = v1 - mean, d2 = v2 - mean;
    float var = block_reduce_sum(d0*d0 + d1*d1 + d2*d2, red) * (1.0f / C_);
    float rs = 1.0f / sqrtf(var + LN_EPS);
    float* y = out + (size_t)row * C_;
    y[tid]       = d0 * rs * g[tid]       + b[tid];
    y[tid + 256] = d1 * rs * g[tid + 256] + b[tid + 256];
    y[tid + 512] = d2 * rs * g[tid + 512] + b[tid + 512];
}

// ---------------- generic fp32 SGEMM (attention path only) ----------------
template<int BM, int BN, int BK, int TM, int TN, int EPI>
__global__ void sgemm_k(const float* __restrict__ A, int lda,
                        const int* __restrict__ gather,
                        const float* __restrict__ Bm, int ldb, size_t bzs,
                        const float* __restrict__ bias,
                        const float* __restrict__ res,
                        float* __restrict__ Cm, int ldc, size_t czs,
                        int M, const int* __restrict__ Mp, int N, int K) {
    constexpr int THREADS = (BM/TM) * (BN/TN);
    if (Mp) M = *Mp;
    int m0 = blockIdx.y * BM;
    if (m0 >= M) return;
    int n0 = blockIdx.x * BN;
    Bm += (size_t)blockIdx.z * bzs;
    Cm += (size_t)blockIdx.z * czs;

    __shared__ float As[BK][BM + 4];
    __shared__ float Bs[BK][BN];
    __shared__ int   ridx[BM];

    int tid = threadIdx.x;
    for (int i = tid; i < BM; i += THREADS) {
        int r = m0 + i;
        ridx[i] = (r < M) ? (gather ? gather[r] : r) : -1;
    }
    __syncthreads();

    int tx = tid % (BN/TN), ty = tid / (BN/TN);
    float acc[TM][TN] = {};
    constexpr int LA4 = (BM*BK) / (THREADS*4);
    constexpr int LB4 = (BK*BN) / (THREADS*4);

    for (int k0 = 0; k0 < K; k0 += BK) {
        #pragma unroll
        for (int i = 0; i < LA4; i++) {
            int idx = (tid + i*THREADS) * 4;
            int ar = idx / BK, ac = idx % BK;
            int gr = ridx[ar];
            float4 v = make_float4(0.f, 0.f, 0.f, 0.f);
            if (gr >= 0) v = *(const float4*)(A + (size_t)gr*lda + k0 + ac);
            As[ac+0][ar] = v.x; As[ac+1][ar] = v.y;
            As[ac+2][ar] = v.z; As[ac+3][ar] = v.w;
        }
        #pragma unroll
        for (int i = 0; i < LB4; i++) {
            int idx = (tid + i*THREADS) * 4;
            int br = idx / BN, bc = idx % BN;
            *(float4*)&Bs[br][bc] = *(const float4*)(Bm + (size_t)(k0+br)*ldb + n0 + bc);
        }
        __syncthreads();
        #pragma unroll
        for (int kk = 0; kk < BK; kk++) {
            float ra[TM], rb[TN];
            #pragma unroll
            for (int i = 0; i < TM; i++) ra[i] = As[kk][ty*TM + i];
            #pragma unroll
            for (int j = 0; j < TN; j++) rb[j] = Bs[kk][tx*TN + j];
            #pragma unroll
            for (int i = 0; i < TM; i++)
                #pragma unroll
                for (int j = 0; j < TN; j++)
                    acc[i][j] += ra[i] * rb[j];
        }
        __syncthreads();
    }
    #pragma unroll
    for (int i = 0; i < TM; i++) {
        int r = m0 + ty*TM + i;
        if (r >= M) continue;
        #pragma unroll
        for (int j = 0; j < TN; j++) {
            int c = n0 + tx*TN + j;
            if (c >= N) continue;
            float v = acc[i][j];
            if (bias) v += bias[c];
            if (EPI == 1) v = gelu_f(v);
            if (EPI == 2) v += res[(size_t)r*ldc + c];
            Cm[(size_t)r*ldc + c] = v;
        }
    }
}

// ---------------- tf32 tensor-core GEMM, 3-stage cp.async + ldmatrix A ----------------
// C[M,N] = A[M,K] @ B[K,N] + bias, EPI: 0 plain, 1 gelu.
// 128x128x32 CTA tile, 8 warps of 64x32, mma.sync.m16n8k8.tf32 (raw fp32 bits).
// A fragments via ldmatrix.x4 (1 instr replaces 16 LDS.32 per k8 step).
#define LDA_S 36     // A smem row stride (floats): conflict-free LDSM/frag loads
#define LDB_S 132    // B smem row stride
#define STG_F 8832   // floats per stage: 128*36 + 32*132
#define TF32_SMEM (3 * STG_F * 4)

__device__ __forceinline__ void cp_tile(uint32_t sb, const float* __restrict__ A, int lda,
                                        const int* __restrict__ ridx,
                                        const float* __restrict__ Bm, int ldb,
                                        int n0, int k0, int tid) {
    #pragma unroll
    for (int i = 0; i < 4; i++) {            // A: 128 rows x 32 floats = 1024 x 16B
        int idx = tid + i*256;
        int row = idx >> 3, c4 = (idx & 7) << 2;
        int gr = ridx[row];
        uint32_t dst = sb + (uint32_t)(row*LDA_S + c4) * 4u;
        const float* src = A + (size_t)(gr < 0 ? 0 : gr)*lda + k0 + c4;
        int sz = (gr >= 0) ? 16 : 0;
        asm volatile("cp.async.cg.shared.global [%0], [%1], 16, %2;"
                     :: "r"(dst), "l"(src), "r"(sz));
    }
    #pragma unroll
    for (int i = 0; i < 4; i++) {            // B: 32 rows x 128 floats = 1024 x 16B
        int idx = tid + i*256;
        int kr = idx >> 5, c4 = (idx & 31) << 2;
        uint32_t dst = sb + (uint32_t)(4608 + kr*LDB_S + c4) * 4u;
        const float* src = Bm + (size_t)(k0+kr)*ldb + n0 + c4;
        asm volatile("cp.async.cg.shared.global [%0], [%1], 16;"
                     :: "r"(dst), "l"(src));
    }
}

template<int EPI>
__global__ void __launch_bounds__(256, 2)
tf32_gemm(const float* __restrict__ A, int lda,
          const int* __restrict__ gather,
          const float* __restrict__ Bm, int ldb,
          const float* __restrict__ bias,
          float* __restrict__ Cm, int ldc,
          const int* __restrict__ Mp, int N, int K) {
    constexpr int BM = 128, BK = 32;
    extern __shared__ float dsm[];
    __shared__ int ridx[BM];

    const int M = *Mp;
    int m0 = blockIdx.y * BM;
    if (m0 >= M) return;
    int n0 = blockIdx.x * 128;

    int tid = threadIdx.x;
    int lane = tid & 31, wid = tid >> 5;
    int wm = (wid & 1) * 64;
    int wn = (wid >> 1) * 32;
    int lr = lane >> 2;
    int lc = lane & 3;

    for (int i = tid; i < BM; i += 256) {
        int r = m0 + i;
        ridx[i] = (r < M) ? (gather ? gather[r] : r) : -1;
    }
    __syncthreads();

    uint32_t sbase;
    { unsigned long long gp = __cvta_generic_to_shared(dsm); sbase = (uint32_t)gp; }

    // ldmatrix lane->address map for A fragments (byte offsets within stage):
    // lanes[0:8)->rows rb+0..7 col k8 | [8:16)->rb+8..15 col k8
    // [16:24)->rb+0..7 col k8+4      | [24:32)->rb+8..15 col k8+4
    int grp = lane >> 3, lrw = lane & 7;
    uint32_t a_off[4];
    #pragma unroll
    for (int mt = 0; mt < 4; mt++)
        a_off[mt] = (uint32_t)((wm + mt*16 + (grp & 1)*8 + lrw) * LDA_S + (grp >> 1)*4) * 4u;

    const int iters = K / BK;
    // prologue: stages 0,1
    cp_tile(sbase + 0*STG_F*4, A, lda, ridx, Bm, ldb, n0, 0, tid);
    asm volatile("cp.async.commit_group;");
    if (iters > 1) cp_tile(sbase + 1*STG_F*4, A, lda, ridx, Bm, ldb, n0, BK, tid);
    asm volatile("cp.async.commit_group;");

    float acc[4][4][4];
    #pragma unroll
    for (int mt = 0; mt < 4; mt++)
        #pragma unroll
        for (int nt = 0; nt < 4; nt++)
            #pragma unroll
            for (int i = 0; i < 4; i++) acc[mt][nt][i] = 0.f;

    int st = 0;
    for (int it = 0; it < iters; it++) {
        asm volatile("cp.async.wait_group 1;");
        __syncthreads();
        // prefetch stage it+2
        if (it + 2 < iters) {
            int ps = (st + 2 >= 3) ? st - 1 : st + 2;
            cp_tile(sbase + (uint32_t)ps*STG_F*4, A, lda, ridx, Bm, ldb, n0, (it+2)*BK, tid);
        }
        asm volatile("cp.async.commit_group;");

        uint32_t As_b = sbase + (uint32_t)st * (STG_F * 4u);
        const float* Bs = dsm + (size_t)st * STG_F + 4608;
        #pragma unroll
        for (int k8 = 0; k8 < 4; k8++) {
            uint32_t a[4][4], b[4][2];
            #pragma unroll
            for (int mt = 0; mt < 4; mt++)
                ldsm_x4(a[mt], As_b + a_off[mt] + (uint32_t)k8 * 32u);
            #pragma unroll
            for (int nt = 0; nt < 4; nt++) {
                b[nt][0] = __float_as_uint(Bs[(k8*8 + lc    )*LDB_S + wn + nt*8 + lr]);
                b[nt][1] = __float_as_uint(Bs[(k8*8 + 4 + lc)*LDB_S + wn + nt*8 + lr]);
            }
            #pragma unroll
            for (int mt = 0; mt < 4; mt++)
                #pragma unroll
                for (int nt = 0; nt < 4; nt++)
                    mma_tf32(acc[mt][nt], a[mt], b[nt]);
        }
        st = (st + 1 >= 3) ? 0 : st + 1;
    }

    // epilogue: bias (+gelu), float2 stores
    #pragma unroll
    for (int mt = 0; mt < 4; mt++) {
        int r0 = m0 + wm + mt*16 + lr;
        int r1 = r0 + 8;
        #pragma unroll
        for (int nt = 0; nt < 4; nt++) {
            int c = n0 + wn + nt*8 + lc*2;
            float bz0 = bias[c], bz1 = bias[c+1];
            float v0 = acc[mt][nt][0] + bz0, v1 = acc[mt][nt][1] + bz1;
            float v2 = acc[mt][nt][2] + bz0, v3 = acc[mt][nt][3] + bz1;
            if (EPI == 1) { v0 = gelu_f(v0); v1 = gelu_f(v1); v2 = gelu_f(v2); v3 = gelu_f(v3); }
            if (r0 < M) *(float2*)(Cm + (size_t)r0*ldc + c) = make_float2(v0, v1);
            if (r1 < M) *(float2*)(Cm + (size_t)r1*ldc + c) = make_float2(v2, v3);
        }
    }
}

// ---------------- flash attention (fp32, causal, BQ=64, BKV=32, D=64) ----------------
__global__ void flash_kernel(const float* __restrict__ Q, const float* __restrict__ Kg,
                             const float* __restrict__ Vg, float* __restrict__ O) {
    constexpr int BQ = 64, BKV = 32;
    int qi = blockIdx.x;
    int bh = blockIdx.y;
    int b = bh / H_, h = bh % H_;
    const float* Qb = Q  + ((size_t)h*N_ + (size_t)b*T_) * HS_;
    const float* Kb = Kg + ((size_t)h*N_ + (size_t)b*T_) * HS_;
    const float* Vb = Vg + ((size_t)h*N_ + (size_t)b*T_) * HS_;

    __shared__ float Qs[BQ][HS_+4];
    __shared__ float Ks[BKV][HS_+4];
    __shared__ float Vs[BKV][HS_+4];
    __shared__ float Ps[BQ][BKV+4];
    __shared__ float mrow[BQ], lrow[BQ];
    __shared__ float redm[BQ][4], reds[BQ][4];

    int tid = threadIdx.x;
    for (int i = tid; i < BQ*HS_/4; i += 256) {
        int idx = i * 4; int r = idx / HS_, c = idx % HS_;
        float4 v = *(const float4*)(Qb + (size_t)(qi*BQ + r)*HS_ + c);
        Qs[r][c+0] = v.x * ATT_SCALE; Qs[r][c+1] = v.y * ATT_SCALE;
        Qs[r][c+2] = v.z * ATT_SCALE; Qs[r][c+3] = v.w * ATT_SCALE;
    }
    if (tid < BQ) { mrow[tid] = -INFINITY; lrow[tid] = 0.f; }

    int r = tid / 4, cg = tid % 4;
    int rg = qi*BQ + r;
    float Oacc[16];
    #pragma unroll
    for (int i = 0; i < 16; i++) Oacc[i] = 0.f;

    int jmax = 2*qi + 1;
    for (int j = 0; j <= jmax; j++) {
        __syncthreads();
        for (int i = tid; i < BKV*HS_/4; i += 256) {
            int idx = i * 4; int rr = idx / HS_, c = idx % HS_;
            float4 kv = *(const float4*)(Kb + (size_t)(j*BKV + rr)*HS_ + c);
            Ks[rr][c+0] = kv.x; Ks[rr][c+1] = kv.y; Ks[rr][c+2] = kv.z; Ks[rr][c+3] = kv.w;
            float4 vv = *(const float4*)(Vb + (size_t)(j*BKV + rr)*HS_ + c);
            Vs[rr][c+0] = vv.x; Vs[rr][c+1] = vv.y; Vs[rr][c+2] = vv.z; Vs[rr][c+3] = vv.w;
        }
        __syncthreads();

        float s[8];
        #pragma unroll
        for (int i = 0; i < 8; i++) s[i] = 0.f;
        #pragma unroll
        for (int d0 = 0; d0 < HS_; d0 += 16) {
            float qreg[16];
            #pragma unroll
            for (int d = 0; d < 16; d++) qreg[d] = Qs[r][d0+d];
            #pragma unroll
            for (int i = 0; i < 8; i++) {
                int c = cg*8 + i;
                #pragma unroll
                for (int d = 0; d < 16; d++)
                    s[i] += qreg[d] * Ks[c][d0+d];
            }
        }
        float lm = -INFINITY;
        #pragma unroll
        for (int i = 0; i < 8; i++) {
            int cgl = j*BKV + cg*8 + i;
            if (cgl > rg) s[i] = -INFINITY;
            lm = fmaxf(lm, s[i]);
        }
        redm[r][cg] = lm;
        __syncthreads();
        float mprev = mrow[r];
        float mnew = fmaxf(fmaxf(redm[r][0], redm[r][1]), fmaxf(redm[r][2], redm[r][3]));
        mnew = fmaxf(mprev, mnew);
        float ls = 0.f;
        #pragma unroll
        for (int i = 0; i < 8; i++) {
            float p = expf(s[i] - mnew);
            Ps[r][cg*8 + i] = p;
            ls += p;
        }
        reds[r][cg] = ls;
        float alpha = expf(mprev - mnew);
        __syncthreads();
        if (cg == 0) {
            float totl = reds[r][0] + reds[r][1] + reds[r][2] + reds[r][3];
            lrow[r] = lrow[r] * alpha + totl;
            mrow[r] = mnew;
        }
        #pragma unroll
        for (int d = 0; d < 16; d++) Oacc[d] *= alpha;
        #pragma unroll
        for (int c = 0; c < BKV; c++) {
            float p = Ps[r][c];
            #pragma unroll
            for (int d = 0; d < 16; d++)
                Oacc[d] += p * Vs[c][cg*16 + d];
        }
    }
    __syncthreads();
    float inv = 1.0f / lrow[r];
    float* orow = O + (size_t)(b*T_ + qi*BQ + r) * C_ + h*HS_ + cg*16;
    #pragma unroll
    for (int d = 0; d < 16; d++) orow[d] = Oacc[d] * inv;
}

// ---------------- reset router counters ----------------
__global__ void zero_cnt_kernel() {
    if (threadIdx.x < E_) g_cnt[threadIdx.x] = 0;
}

// ---------------- noisy top-2 router; builds per-expert token lists ----------------
__global__ void router_kernel(const float* __restrict__ h2,
                              const float* __restrict__ w_route, const float* __restrict__ b_route,
                              const float* __restrict__ w_noise, const float* __restrict__ b_noise,
                              const float* __restrict__ temp_p, const float* __restrict__ rnoise) {
    int n = blockIdx.x, tid = threadIdx.x;
    __shared__ float hrow[C_];
    __shared__ float sums[16];
    for (int i = tid; i < C_; i += 256) hrow[i] = h2[(size_t)n*C_ + i];
    __syncthreads();
    int w = tid / 32, lane = tid % 32;
    float sr = 0.f, sn = 0.f;
    for (int c = lane; c < C_; c += 32) {
        float hv = hrow[c];
        sr += hv * w_route[c*E_ + w];
        sn += hv * w_noise[c*E_ + w];
    }
    #pragma unroll
    for (int o = 16; o > 0; o >>= 1) {
        sr += __shfl_down_sync(0xffffffffu, sr, o);
        sn += __shfl_down_sync(0xffffffffu, sn, o);
    }
    if (lane == 0) { sums[w] = sr; sums[8 + w] = sn; }
    __syncthreads();
    if (tid == 0) {
        float temp = fminf(fmaxf(temp_p[0], 0.5f), 2.0f);
        float noisy[E_];
        #pragma unroll
        for (int e = 0; e < E_; e++) {
            float logit = sums[e] + b_route[e];
            float z = sums[8 + e] + b_noise[e];
            float sp = (z > 20.f) ? z : log1pf(expf(z));
            noisy[e] = logit + temp * rnoise[(size_t)n*E_ + e] * sp;
        }
        int i0 = 0; float v0 = noisy[0];
        #pragma unroll
        for (int e = 1; e < E_; e++) if (noisy[e] > v0) { v0 = noisy[e]; i0 = e; }
        int i1 = -1; float v1 = -INFINITY;
        #pragma unroll
        for (int e = 0; e < E_; e++) if (e != i0 && noisy[e] > v1) { v1 = noisy[e]; i1 = e; }
        float eb = expf(v1 - v0);
        float gg0 = 1.0f / (1.0f + eb);
        float gg1 = eb / (1.0f + eb);
        int s0 = atomicAdd(&g_cnt[i0], 1);
        int s1 = atomicAdd(&g_cnt[i1], 1);
        g_tok[i0*N_ + s0] = n;  g_tok[i1*N_ + s1] = n;
        g_texp [n*2] = i0;      g_texp [n*2+1] = i1;
        g_tslot[n*2] = s0;      g_tslot[n*2+1] = s1;
        g_tgate[n*2] = gg0;     g_tgate[n*2+1] = gg1;
    }
}

// ---------------- final: per-token expert residual-LN + gated combine ----------------
__global__ void final_kernel(const float* __restrict__ x1, const float* __restrict__ h2,
                             const float* __restrict__ dlg, const float* __restrict__ dlb,
                             const float* __restrict__ slg, const float* __restrict__ slb,
                             float* __restrict__ out) {
    __shared__ float red[256];
    int n = blockIdx.x, tid = threadIdx.x;
    const float* hr = h2 + (size_t)n*C_;
    float h0 = hr[tid], h1 = hr[tid+256], h2v = hr[tid+512];
    float a0 = 0.f, a1 = 0.f, a2 = 0.f;
    for (int jj = 0; jj < 2; jj++) {
        int e = g_texp[n*2 + jj];
        int s = g_tslot[n*2 + jj];
        float gt = g_tgate[n*2 + jj];
        const float* y = g_y + ((size_t)e*N_ + s) * C_;
        float z0 = h0 + y[tid], z1 = h1 + y[tid+256], z2 = h2v + y[tid+512];
        float mean = block_reduce_sum(z0 + z1 + z2, red) * (1.0f / C_);
        float d0 = z0 - mean, d1 = z1 - mean, d2 = z2 - mean;
        float var = block_reduce_sum(d0*d0 + d1*d1 + d2*d2, red) * (1.0f / C_);
        float rs = 1.0f / sqrtf(var + LN_EPS);
        const float* gam; const float* bet;
        if (e < 2) { gam = dlg + e*C_;       bet = dlb + e*C_; }
        else       { gam = slg + (e-2)*C_;   bet = slb + (e-2)*C_; }
        a0 += gt * (d0*rs*gam[tid]     + bet[tid]);
        a1 += gt * (d1*rs*gam[tid+256] + bet[tid+256]);
        a2 += gt * (d2*rs*gam[tid+512] + bet[tid+512]);
    }
    const float* xr = x1 + (size_t)n*C_;
    float* orow = out + (size_t)n*C_;
    orow[tid]     = xr[tid]     + a0;
    orow[tid+256] = xr[tid+256] + a1;
    orow[tid+512] = xr[tid+512] + a2;
}

// ---------------- host ----------------
extern "C" void kernel_launch(void* const* d_in, const int* in_sizes, int n_in,
                              void* d_out, int out_size) {
    const float* x          = (const float*)d_in[0];
    const float* rnoise     = (const float*)d_in[1];
    const float* wq         = (const float*)d_in[2];
    const float* wk         = (const float*)d_in[3];
    const float* wv         = (const float*)d_in[4];
    const float* w_proj     = (const float*)d_in[5];
    const float* b_proj     = (const float*)d_in[6];
    const float* ln1_g      = (const float*)d_in[7];
    const float* ln1_b      = (const float*)d_in[8];
    const float* ln2_g      = (const float*)d_in[9];
    const float* ln2_b      = (const float*)d_in[10];
    const float* w_route    = (const float*)d_in[11];
    const float* b_route    = (const float*)d_in[12];
    const float* w_noise    = (const float*)d_in[13];
    const float* b_noise    = (const float*)d_in[14];
    const float* temp       = (const float*)d_in[15];
    const float* deep_w1    = (const float*)d_in[16];
    const float* deep_b1    = (const float*)d_in[17];
    const float* deep_w2    = (const float*)d_in[18];
    const float* deep_b2    = (const float*)d_in[19];
    const float* deep_w3    = (const float*)d_in[20];
    const float* deep_b3    = (const float*)d_in[21];
    const float* deep_ln_g  = (const float*)d_in[22];
    const float* deep_ln_b  = (const float*)d_in[23];
    const float* simple_w1  = (const float*)d_in[24];
    const float* simple_b1  = (const float*)d_in[25];
    const float* simple_w2  = (const float*)d_in[26];
    const float* simple_b2  = (const float*)d_in[27];
    const float* simple_ln_g= (const float*)d_in[28];
    const float* simple_ln_b= (const float*)d_in[29];
    float* out = (float*)d_out;

    float *ph, *pq, *pk, *pv, *po, *px1, *ph2, *pa1, *pa2, *py;
    int *pcnt, *ptok;
    cudaGetSymbolAddress((void**)&ph,  g_h);
    cudaGetSymbolAddress((void**)&pq,  g_q);
    cudaGetSymbolAddress((void**)&pk,  g_k);
    cudaGetSymbolAddress((void**)&pv,  g_v);
    cudaGetSymbolAddress((void**)&po,  g_o);
    cudaGetSymbolAddress((void**)&px1, g_x1);
    cudaGetSymbolAddress((void**)&ph2, g_h2);
    cudaGetSymbolAddress((void**)&pa1, g_a1);
    cudaGetSymbolAddress((void**)&pa2, g_a2);
    cudaGetSymbolAddress((void**)&py,  g_y);
    cudaGetSymbolAddress((void**)&pcnt, g_cnt);
    cudaGetSymbolAddress((void**)&ptok, g_tok);

    // opt-in to >48KB dynamic smem (host-side attribute set; not a stream op)
    cudaFuncSetAttribute(tf32_gemm<0>, cudaFuncAttributeMaxDynamicSharedMemorySize, TF32_SMEM);
    cudaFuncSetAttribute(tf32_gemm<1>, cudaFuncAttributeMaxDynamicSharedMemorySize, TF32_SMEM);

    // 1) LN1
    ln_kernel<<<N_, 256>>>(x, ln1_g, ln1_b, ph);

    // 2) QKV (fp32 — feeds router path, keep exact)
    {
        dim3 grid(1, N_/128, H_);
        sgemm_k<128,64,16,8,4,0><<<grid, 256>>>(ph, C_, nullptr,
            wq, HS_, (size_t)C_*HS_, nullptr, nullptr,
            pq, HS_, (size_t)N_*HS_, N_, nullptr, HS_, C_);
        sgemm_k<128,64,16,8,4,0><<<grid, 256>>>(ph, C_, nullptr,
            wk, HS_, (size_t)C_*HS_, nullptr, nullptr,
            pk, HS_, (size_t)N_*HS_, N_, nullptr, HS_, C_);
        sgemm_k<128,64,16,8,4,0><<<grid, 256>>>(ph, C_, nullptr,
            wv, HS_, (size_t)C_*HS_, nullptr, nullptr,
            pv, HS_, (size_t)N_*HS_, N_, nullptr, HS_, C_);
    }

    // 3) causal flash attention (fp32)
    flash_kernel<<<dim3(T_/64, B_*H_), 256>>>(pq, pk, pv, po);

    // 4) out proj + residual (fp32 — feeds router path)
    sgemm_k<128,128,16,8,8,2><<<dim3(C_/128, N_/128), 256>>>(po, C_, nullptr,
        w_proj, C_, 0, b_proj, x, px1, C_, 0, N_, nullptr, C_, C_);

    // 5) LN2
    ln_kernel<<<N_, 256>>>(px1, ln2_g, ln2_b, ph2);

    // 6) router (fp32)
    zero_cnt_kernel<<<1, 32>>>();
    router_kernel<<<N_, 256>>>(ph2, w_route, b_route, w_noise, b_noise, temp, rnoise);

    // 7) expert first layer (gathered rows), GELU epilogue — tf32 pipelined
    for (int e = 0; e < E_; e++) {
        const float* W1 = (e < 2) ? deep_w1 + (size_t)e*C_*F_ : simple_w1 + (size_t)(e-2)*C_*F_;
        const float* B1 = (e < 2) ? deep_b1 + (size_t)e*F_    : simple_b1 + (size_t)(e-2)*F_;
        tf32_gemm<1><<<dim3(F_/128, N_/128), 256, TF32_SMEM>>>(
            ph2, C_, ptok + (size_t)e*N_, W1, F_, B1,
            pa1 + (size_t)e*N_*F_, F_, pcnt + e, F_, C_);
    }
    // 8) deep second layer, GELU — tf32 pipelined
    for (int e = 0; e < 2; e++) {
        tf32_gemm<1><<<dim3(F_/128, N_/128), 256, TF32_SMEM>>>(
            pa1 + (size_t)e*N_*F_, F_, nullptr, deep_w2 + (size_t)e*F_*F_, F_,
            deep_b2 + (size_t)e*F_,
            pa2 + (size_t)e*N_*F_, F_, pcnt + e, F_, F_);
    }
    // 9) expert output layer -> y — tf32 pipelined
    for (int e = 0; e < E_; e++) {
        const float *W, *Bb, *Ain;
        if (e < 2) { W = deep_w3 + (size_t)e*F_*C_;       Bb = deep_b3 + (size_t)e*C_;
                     Ain = pa2 + (size_t)e*N_*F_; }
        else       { W = simple_w2 + (size_t)(e-2)*F_*C_; Bb = simple_b2 + (size_t)(e-2)*C_;
                     Ain = pa1 + (size_t)e*N_*F_; }
        tf32_gemm<0><<<dim3(C_/128, N_/128), 256, TF32_SMEM>>>(
            Ain, F_, nullptr, W, C_, Bb,
            py + (size_t)e*N_*C_, C_, pcnt + e, C_, F_);
    }

    // 10) per-token gated residual-LN combine
    final_kernel<<<N_, 256>>>(px1, ph2, deep_ln_g, deep_ln_b, simple_ln_g, simple_ln_b, out);
}

// round 12
// speedup vs baseline: 2.3467x; 1.0040x over previous
#include <cuda_runtime.h>
#include <math.h>
#include <stdint.h>

// ---------------- problem constants ----------------
#define B_   8
#define T_   1024
#define C_   768
#define H_   12
#define E_   8
#define HS_  64
#define F_   3072
#define N_   (B_*T_)            // 8192 tokens
#define LN_EPS 1e-5f
#define ATT_SCALE 0.03608439182435161f   // 768^-0.5

// ---------------- scratch (static device memory; no allocations) ----------------
__device__ float g_h  [N_*C_];
__device__ float g_q  [H_*N_*HS_];
__device__ float g_k  [H_*N_*HS_];
__device__ float g_v  [H_*N_*HS_];
__device__ float g_o  [N_*C_];
__device__ float g_x1 [N_*C_];
__device__ float g_h2 [N_*C_];
__device__ int   g_cnt[E_];
__device__ int   g_tok[E_*N_];
__device__ int   g_texp [N_*2];
__device__ int   g_tslot[N_*2];
__device__ float g_tgate[N_*2];
__device__ float g_a1[(size_t)E_*N_*F_];   // per-expert hidden
__device__ float g_a2[(size_t)2 *N_*F_];   // deep second hidden
__device__ float g_y [(size_t)E_*N_*C_];   // per-expert pre-LN output

// ---------------- helpers ----------------
__device__ __forceinline__ float gelu_f(float x) {
    return 0.5f * x * (1.0f + erff(x * 0.7071067811865476f));
}

__device__ __forceinline__ void mma_tf32(float* c, const uint32_t* a, const uint32_t* b) {
    asm volatile("mma.sync.aligned.m16n8k8.row.col.f32.tf32.tf32.f32 "
        "{%0,%1,%2,%3}, {%4,%5,%6,%7}, {%8,%9}, {%0,%1,%2,%3};"
        : "+f"(c[0]), "+f"(c[1]), "+f"(c[2]), "+f"(c[3])
        : "r"(a[0]), "r"(a[1]), "r"(a[2]), "r"(a[3]), "r"(b[0]), "r"(b[1]));
}

__device__ __forceinline__ void ldsm_x4(uint32_t* r, uint32_t addr) {
    asm volatile("ldmatrix.sync.aligned.m8n8.x4.shared.b16 {%0,%1,%2,%3}, [%4];"
        : "=r"(r[0]), "=r"(r[1]), "=r"(r[2]), "=r"(r[3]) : "r"(addr));
}

__device__ __forceinline__ float block_reduce_sum(float v, float* red) {
    int tid = threadIdx.x;
    red[tid] = v; __syncthreads();
    #pragma unroll
    for (int o = 128; o > 0; o >>= 1) {
        if (tid < o) red[tid] += red[tid + o];
        __syncthreads();
    }
    float r = red[0];
    __syncthreads();
    return r;
}

// ---------------- LayerNorm over rows of 768, block=256 ----------------
__global__ void ln_kernel(const float* __restrict__ in, const float* __restrict__ g,
                          const float* __restrict__ b, float* __restrict__ out) {
    __shared__ float red[256];
    int row = blockIdx.x, tid = threadIdx.x;
    const float* x = in + (size_t)row * C_;
    float v0 = x[tid], v1 = x[tid + 256], v2 = x[tid + 512];
    float mean = block_reduce_sum(v0 + v1 + v2, red) * (1.0f / C_);
    float d0 = v0 - mean, d1 = v1 - mean, d2 = v2 - mean;
    float var = block_reduce_sum(d0*d0 + d1*d1 + d2*d2, red) * (1.0f / C_);
    float rs = 1.0f / sqrtf(var + LN_EPS);
    float* y = out + (size_t)row * C_;
    y[tid]       = d0 * rs * g[tid]       + b[tid];
    y[tid + 256] = d1 * rs * g[tid + 256] + b[tid + 256];
    y[tid + 512] = d2 * rs * g[tid + 512] + b[tid + 512];
}

// ---------------- generic fp32 SGEMM (attention path only) ----------------
template<int BM, int BN, int BK, int TM, int TN, int EPI>
__global__ void sgemm_k(const float* __restrict__ A, int lda,
                        const int* __restrict__ gather,
                        const float* __restrict__ Bm, int ldb, size_t bzs,
                        const float* __restrict__ bias,
                        const float* __restrict__ res,
                        float* __restrict__ Cm, int ldc, size_t czs,
                        int M, const int* __restrict__ Mp, int N, int K) {
    constexpr int THREADS = (BM/TM) * (BN/TN);
    if (Mp) M = *Mp;
    int m0 = blockIdx.y * BM;
    if (m0 >= M) return;
    int n0 = blockIdx.x * BN;
    Bm += (size_t)blockIdx.z * bzs;
    Cm += (size_t)blockIdx.z * czs;

    __shared__ float As[BK][BM + 4];
    __shared__ float Bs[BK][BN];
    __shared__ int   ridx[BM];

    int tid = threadIdx.x;
    for (int i = tid; i < BM; i += THREADS) {
        int r = m0 + i;
        ridx[i] = (r < M) ? (gather ? gather[r] : r) : -1;
    }
    __syncthreads();

    int tx = tid % (BN/TN), ty = tid / (BN/TN);
    float acc[TM][TN] = {};
    constexpr int LA4 = (BM*BK) / (THREADS*4);
    constexpr int LB4 = (BK*BN) / (THREADS*4);

    for (int k0 = 0; k0 < K; k0 += BK) {
        #pragma unroll
        for (int i = 0; i < LA4; i++) {
            int idx = (tid + i*THREADS) * 4;
            int ar = idx / BK, ac = idx % BK;
            int gr = ridx[ar];
            float4 v = make_float4(0.f, 0.f, 0.f, 0.f);
            if (gr >= 0) v = *(const float4*)(A + (size_t)gr*lda + k0 + ac);
            As[ac+0][ar] = v.x; As[ac+1][ar] = v.y;
            As[ac+2][ar] = v.z; As[ac+3][ar] = v.w;
        }
        #pragma unroll
        for (int i = 0; i < LB4; i++) {
            int idx = (tid + i*THREADS) * 4;
            int br = idx / BN, bc = idx % BN;
            *(float4*)&Bs[br][bc] = *(const float4*)(Bm + (size_t)(k0+br)*ldb + n0 + bc);
        }
        __syncthreads();
        #pragma unroll
        for (int kk = 0; kk < BK; kk++) {
            float ra[TM], rb[TN];
            #pragma unroll
            for (int i = 0; i < TM; i++) ra[i] = As[kk][ty*TM + i];
            #pragma unroll
            for (int j = 0; j < TN; j++) rb[j] = Bs[kk][tx*TN + j];
            #pragma unroll
            for (int i = 0; i < TM; i++)
                #pragma unroll
                for (int j = 0; j < TN; j++)
                    acc[i][j] += ra[i] * rb[j];
        }
        __syncthreads();
    }
    #pragma unroll
    for (int i = 0; i < TM; i++) {
        int r = m0 + ty*TM + i;
        if (r >= M) continue;
        #pragma unroll
        for (int j = 0; j < TN; j++) {
            int c = n0 + tx*TN + j;
            if (c >= N) continue;
            float v = acc[i][j];
            if (bias) v += bias[c];
            if (EPI == 1) v = gelu_f(v);
            if (EPI == 2) v += res[(size_t)r*ldc + c];
            Cm[(size_t)r*ldc + c] = v;
        }
    }
}

// ---------------- tf32 tensor-core GEMM, 3-stage cp.async + ldmatrix A ----------------
// C[M,N] = A[M,K] @ B[K,N] + bias, EPI: 0 plain, 1 gelu.
// 128x128x32 CTA tile, 8 warps of 64x32, mma.sync.m16n8k8.tf32 (raw fp32 bits).
// A fragments via ldmatrix.x4 (1 instr replaces 16 LDS.32 per k8 step).
#define LDA_S 36     // A smem row stride (floats): conflict-free LDSM/frag loads
#define LDB_S 132    // B smem row stride
#define STG_F 8832   // floats per stage: 128*36 + 32*132
#define TF32_SMEM (3 * STG_F * 4)

__device__ __forceinline__ void cp_tile(uint32_t sb, const float* __restrict__ A, int lda,
                                        const int* __restrict__ ridx,
                                        const float* __restrict__ Bm, int ldb,
                                        int n0, int k0, int tid) {
    #pragma unroll
    for (int i = 0; i < 4; i++) {            // A: 128 rows x 32 floats = 1024 x 16B
        int idx = tid + i*256;
        int row = idx >> 3, c4 = (idx & 7) << 2;
        int gr = ridx[row];
        uint32_t dst = sb + (uint32_t)(row*LDA_S + c4) * 4u;
        const float* src = A + (size_t)(gr < 0 ? 0 : gr)*lda + k0 + c4;
        int sz = (gr >= 0) ? 16 : 0;
        asm volatile("cp.async.cg.shared.global [%0], [%1], 16, %2;"
                     :: "r"(dst), "l"(src), "r"(sz));
    }
    #pragma unroll
    for (int i = 0; i < 4; i++) {            // B: 32 rows x 128 floats = 1024 x 16B
        int idx = tid + i*256;
        int kr = idx >> 5, c4 = (idx & 31) << 2;
        uint32_t dst = sb + (uint32_t)(4608 + kr*LDB_S + c4) * 4u;
        const float* src = Bm + (size_t)(k0+kr)*ldb + n0 + c4;
        asm volatile("cp.async.cg.shared.global [%0], [%1], 16;"
                     :: "r"(dst), "l"(src));
    }
}

template<int EPI>
__global__ void __launch_bounds__(256, 2)
tf32_gemm(const float* __restrict__ A, int lda,
          const int* __restrict__ gather,
          const float* __restrict__ Bm, int ldb,
          const float* __restrict__ bias,
          float* __restrict__ Cm, int ldc,
          const int* __restrict__ Mp, int N, int K) {
    constexpr int BM = 128, BK = 32;
    extern __shared__ float dsm[];
    __shared__ int ridx[BM];

    const int M = *Mp;
    int m0 = blockIdx.y * BM;
    if (m0 >= M) return;
    int n0 = blockIdx.x * 128;

    int tid = threadIdx.x;
    int lane = tid & 31, wid = tid >> 5;
    int wm = (wid & 1) * 64;
    int wn = (wid >> 1) * 32;
    int lr = lane >> 2;
    int lc = lane & 3;

    for (int i = tid; i < BM; i += 256) {
        int r = m0 + i;
        ridx[i] = (r < M) ? (gather ? gather[r] : r) : -1;
    }
    __syncthreads();

    uint32_t sbase;
    { unsigned long long gp = __cvta_generic_to_shared(dsm); sbase = (uint32_t)gp; }

    // ldmatrix lane->address map for A fragments (byte offsets within stage):
    // lanes[0:8)->rows rb+0..7 col k8 | [8:16)->rb+8..15 col k8
    // [16:24)->rb+0..7 col k8+4      | [24:32)->rb+8..15 col k8+4
    int grp = lane >> 3, lrw = lane & 7;
    uint32_t a_off[4];
    #pragma unroll
    for (int mt = 0; mt < 4; mt++)
        a_off[mt] = (uint32_t)((wm + mt*16 + (grp & 1)*8 + lrw) * LDA_S + (grp >> 1)*4) * 4u;

    const int iters = K / BK;
    // prologue: stages 0,1
    cp_tile(sbase + 0*STG_F*4, A, lda, ridx, Bm, ldb, n0, 0, tid);
    asm volatile("cp.async.commit_group;");
    if (iters > 1) cp_tile(sbase + 1*STG_F*4, A, lda, ridx, Bm, ldb, n0, BK, tid);
    asm volatile("cp.async.commit_group;");

    float acc[4][4][4];
    #pragma unroll
    for (int mt = 0; mt < 4; mt++)
        #pragma unroll
        for (int nt = 0; nt < 4; nt++)
            #pragma unroll
            for (int i = 0; i < 4; i++) acc[mt][nt][i] = 0.f;

    int st = 0;
    for (int it = 0; it < iters; it++) {
        asm volatile("cp.async.wait_group 1;");
        __syncthreads();
        // prefetch stage it+2
        if (it + 2 < iters) {
            int ps = (st + 2 >= 3) ? st - 1 : st + 2;
            cp_tile(sbase + (uint32_t)ps*STG_F*4, A, lda, ridx, Bm, ldb, n0, (it+2)*BK, tid);
        }
        asm volatile("cp.async.commit_group;");

        uint32_t As_b = sbase + (uint32_t)st * (STG_F * 4u);
        const float* Bs = dsm + (size_t)st * STG_F + 4608;
        #pragma unroll
        for (int k8 = 0; k8 < 4; k8++) {
            uint32_t a[4][4], b[4][2];
            #pragma unroll
            for (int mt = 0; mt < 4; mt++)
                ldsm_x4(a[mt], As_b + a_off[mt] + (uint32_t)k8 * 32u);
            #pragma unroll
            for (int nt = 0; nt < 4; nt++) {
                b[nt][0] = __float_as_uint(Bs[(k8*8 + lc    )*LDB_S + wn + nt*8 + lr]);
                b[nt][1] = __float_as_uint(Bs[(k8*8 + 4 + lc)*LDB_S + wn + nt*8 + lr]);
            }
            #pragma unroll
            for (int mt = 0; mt < 4; mt++)
                #pragma unroll
                for (int nt = 0; nt < 4; nt++)
                    mma_tf32(acc[mt][nt], a[mt], b[nt]);
        }
        st = (st + 1 >= 3) ? 0 : st + 1;
    }

    // epilogue: bias (+gelu), float2 stores
    #pragma unroll
    for (int mt = 0; mt < 4; mt++) {
        int r0 = m0 + wm + mt*16 + lr;
        int r1 = r0 + 8;
        #pragma unroll
        for (int nt = 0; nt < 4; nt++) {
            int c = n0 + wn + nt*8 + lc*2;
            float bz0 = bias[c], bz1 = bias[c+1];
            float v0 = acc[mt][nt][0] + bz0, v1 = acc[mt][nt][1] + bz1;
            float v2 = acc[mt][nt][2] + bz0, v3 = acc[mt][nt][3] + bz1;
            if (EPI == 1) { v0 = gelu_f(v0); v1 = gelu_f(v1); v2 = gelu_f(v2); v3 = gelu_f(v3); }
            if (r0 < M) *(float2*)(Cm + (size_t)r0*ldc + c) = make_float2(v0, v1);
            if (r1 < M) *(float2*)(Cm + (size_t)r1*ldc + c) = make_float2(v2, v3);
        }
    }
}

// ---------------- flash attention (fp32, causal, BQ=64, BKV=32, D=64) ----------------
__global__ void flash_kernel(const float* __restrict__ Q, const float* __restrict__ Kg,
                             const float* __restrict__ Vg, float* __restrict__ O) {
    constexpr int BQ = 64, BKV = 32;
    int qi = blockIdx.x;
    int bh = blockIdx.y;
    int b = bh / H_, h = bh % H_;
    const float* Qb = Q  + ((size_t)h*N_ + (size_t)b*T_) * HS_;
    const float* Kb = Kg + ((size_t)h*N_ + (size_t)b*T_) * HS_;
    const float* Vb = Vg + ((size_t)h*N_ + (size_t)b*T_) * HS_;

    __shared__ float Qs[BQ][HS_+4];
    __shared__ float Ks[BKV][HS_+4];
    __shared__ float Vs[BKV][HS_+4];
    __shared__ float Ps[BQ][BKV+4];
    __shared__ float mrow[BQ], lrow[BQ];
    __shared__ float redm[BQ][4], reds[BQ][4];

    int tid = threadIdx.x;
    for (int i = tid; i < BQ*HS_/4; i += 256) {
        int idx = i * 4; int r = idx / HS_, c = idx % HS_;
        float4 v = *(const float4*)(Qb + (size_t)(qi*BQ + r)*HS_ + c);
        Qs[r][c+0] = v.x * ATT_SCALE; Qs[r][c+1] = v.y * ATT_SCALE;
        Qs[r][c+2] = v.z * ATT_SCALE; Qs[r][c+3] = v.w * ATT_SCALE;
    }
    if (tid < BQ) { mrow[tid] = -INFINITY; lrow[tid] = 0.f; }

    int r = tid / 4, cg = tid % 4;
    int rg = qi*BQ + r;
    float Oacc[16];
    #pragma unroll
    for (int i = 0; i < 16; i++) Oacc[i] = 0.f;

    int jmax = 2*qi + 1;
    for (int j = 0; j <= jmax; j++) {
        __syncthreads();
        for (int i = tid; i < BKV*HS_/4; i += 256) {
            int idx = i * 4; int rr = idx / HS_, c = idx % HS_;
            float4 kv = *(const float4*)(Kb + (size_t)(j*BKV + rr)*HS_ + c);
            Ks[rr][c+0] = kv.x; Ks[rr][c+1] = kv.y; Ks[rr][c+2] = kv.z; Ks[rr][c+3] = kv.w;
            float4 vv = *(const float4*)(Vb + (size_t)(j*BKV + rr)*HS_ + c);
            Vs[rr][c+0] = vv.x; Vs[rr][c+1] = vv.y; Vs[rr][c+2] = vv.z; Vs[rr][c+3] = vv.w;
        }
        __syncthreads();

        float s[8];
        #pragma unroll
        for (int i = 0; i < 8; i++) s[i] = 0.f;
        #pragma unroll
        for (int d0 = 0; d0 < HS_; d0 += 16) {
            float qreg[16];
            #pragma unroll
            for (int d = 0; d < 16; d++) qreg[d] = Qs[r][d0+d];
            #pragma unroll
            for (int i = 0; i < 8; i++) {
                int c = cg*8 + i;
                #pragma unroll
                for (int d = 0; d < 16; d++)
                    s[i] += qreg[d] * Ks[c][d0+d];
            }
        }
        float lm = -INFINITY;
        #pragma unroll
        for (int i = 0; i < 8; i++) {
            int cgl = j*BKV + cg*8 + i;
            if (cgl > rg) s[i] = -INFINITY;
            lm = fmaxf(lm, s[i]);
        }
        redm[r][cg] = lm;
        __syncthreads();
        float mprev = mrow[r];
        float mnew = fmaxf(fmaxf(redm[r][0], redm[r][1]), fmaxf(redm[r][2], redm[r][3]));
        mnew = fmaxf(mprev, mnew);
        float ls = 0.f;
        #pragma unroll
        for (int i = 0; i < 8; i++) {
            float p = expf(s[i] - mnew);
            Ps[r][cg*8 + i] = p;
            ls += p;
        }
        reds[r][cg] = ls;
        float alpha = expf(mprev - mnew);
        __syncthreads();
        if (cg == 0) {
            float totl = reds[r][0] + reds[r][1] + reds[r][2] + reds[r][3];
            lrow[r] = lrow[r] * alpha + totl;
            mrow[r] = mnew;
        }
        #pragma unroll
        for (int d = 0; d < 16; d++) Oacc[d] *= alpha;
        #pragma unroll
        for (int c = 0; c < BKV; c++) {
            float p = Ps[r][c];
            #pragma unroll
            for (int d = 0; d < 16; d++)
                Oacc[d] += p * Vs[c][cg*16 + d];
        }
    }
    __syncthreads();
    float inv = 1.0f / lrow[r];
    float* orow = O + (size_t)(b*T_ + qi*BQ + r) * C_ + h*HS_ + cg*16;
    #pragma unroll
    for (int d = 0; d < 16; d++) orow[d] = Oacc[d] * inv;
}

// ---------------- reset router counters ----------------
__global__ void zero_cnt_kernel() {
    if (threadIdx.x < E_) g_cnt[threadIdx.x] = 0;
}

// ---------------- noisy top-2 router; builds per-expert token lists ----------------
__global__ void router_kernel(const float* __restrict__ h2,
                              const float* __restrict__ w_route, const float* __restrict__ b_route,
                              const float* __restrict__ w_noise, const float* __restrict__ b_noise,
                              const float* __restrict__ temp_p, const float* __restrict__ rnoise) {
    int n = blockIdx.x, tid = threadIdx.x;
    __shared__ float hrow[C_];
    __shared__ float sums[16];
    for (int i = tid; i < C_; i += 256) hrow[i] = h2[(size_t)n*C_ + i];
    __syncthreads();
    int w = tid / 32, lane = tid % 32;
    float sr = 0.f, sn = 0.f;
    for (int c = lane; c < C_; c += 32) {
        float hv = hrow[c];
        sr += hv * w_route[c*E_ + w];
        sn += hv * w_noise[c*E_ + w];
    }
    #pragma unroll
    for (int o = 16; o > 0; o >>= 1) {
        sr += __shfl_down_sync(0xffffffffu, sr, o);
        sn += __shfl_down_sync(0xffffffffu, sn, o);
    }
    if (lane == 0) { sums[w] = sr; sums[8 + w] = sn; }
    __syncthreads();
    if (tid == 0) {
        float temp = fminf(fmaxf(temp_p[0], 0.5f), 2.0f);
        float noisy[E_];
        #pragma unroll
        for (int e = 0; e < E_; e++) {
            float logit = sums[e] + b_route[e];
            float z = sums[8 + e] + b_noise[e];
            float sp = (z > 20.f) ? z : log1pf(expf(z));
            noisy[e] = logit + temp * rnoise[(size_t)n*E_ + e] * sp;
        }
        int i0 = 0; float v0 = noisy[0];
        #pragma unroll
        for (int e = 1; e < E_; e++) if (noisy[e] > v0) { v0 = noisy[e]; i0 = e; }
        int i1 = -1; float v1 = -INFINITY;
        #pragma unroll
        for (int e = 0; e < E_; e++) if (e != i0 && noisy[e] > v1) { v1 = noisy[e]; i1 = e; }
        float eb = expf(v1 - v0);
        float gg0 = 1.0f / (1.0f + eb);
        float gg1 = eb / (1.0f + eb);
        int s0 = atomicAdd(&g_cnt[i0], 1);
        int s1 = atomicAdd(&g_cnt[i1], 1);
        g_tok[i0*N_ + s0] = n;  g_tok[i1*N_ + s1] = n;
        g_texp [n*2] = i0;      g_texp [n*2+1] = i1;
        g_tslot[n*2] = s0;      g_tslot[n*2+1] = s1;
        g_tgate[n*2] = gg0;     g_tgate[n*2+1] = gg1;
    }
}

// ---------------- final: per-token expert residual-LN + gated combine ----------------
__global__ void final_kernel(const float* __restrict__ x1, const float* __restrict__ h2,
                             const float* __restrict__ dlg, const float* __restrict__ dlb,
                             const float* __restrict__ slg, const float* __restrict__ slb,
                             float* __restrict__ out) {
    __shared__ float red[256];
    int n = blockIdx.x, tid = threadIdx.x;
    const float* hr = h2 + (size_t)n*C_;
    float h0 = hr[tid], h1 = hr[tid+256], h2v = hr[tid+512];
    float a0 = 0.f, a1 = 0.f, a2 = 0.f;
    for (int jj = 0; jj < 2; jj++) {
        int e = g_texp[n*2 + jj];
        int s = g_tslot[n*2 + jj];
        float gt = g_tgate[n*2 + jj];
        const float* y = g_y + ((size_t)e*N_ + s) * C_;
        float z0 = h0 + y[tid], z1 = h1 + y[tid+256], z2 = h2v + y[tid+512];
        float mean = block_reduce_sum(z0 + z1 + z2, red) * (1.0f / C_);
        float d0 = z0 - mean, d1 = z1 - mean, d2 = z2 - mean;
        float var = block_reduce_sum(d0*d0 + d1*d1 + d2*d2, red) * (1.0f / C_);
        float rs = 1.0f / sqrtf(var + LN_EPS);
        const float* gam; const float* bet;
        if (e < 2) { gam = dlg + e*C_;       bet = dlb + e*C_; }
        else       { gam = slg + (e-2)*C_;   bet = slb + (e-2)*C_; }
        a0 += gt * (d0*rs*gam[tid]     + bet[tid]);
        a1 += gt * (d1*rs*gam[tid+256] + bet[tid+256]);
        a2 += gt * (d2*rs*gam[tid+512] + bet[tid+512]);
    }
    const float* xr = x1 + (size_t)n*C_;
    float* orow = out + (size_t)n*C_;
    orow[tid]     = xr[tid]     + a0;
    orow[tid+256] = xr[tid+256] + a1;
    orow[tid+512] = xr[tid+512] + a2;
}

// ---------------- host ----------------
extern "C" void kernel_launch(void* const* d_in, const int* in_sizes, int n_in,
                              void* d_out, int out_size) {
    const float* x          = (const float*)d_in[0];
    const float* rnoise     = (const float*)d_in[1];
    const float* wq         = (const float*)d_in[2];
    const float* wk         = (const float*)d_in[3];
    const float* wv         = (const float*)d_in[4];
    const float* w_proj     = (const float*)d_in[5];
    const float* b_proj     = (const float*)d_in[6];
    const float* ln1_g      = (const float*)d_in[7];
    const float* ln1_b      = (const float*)d_in[8];
    const float* ln2_g      = (const float*)d_in[9];
    const float* ln2_b      = (const float*)d_in[10];
    const float* w_route    = (const float*)d_in[11];
    const float* b_route    = (const float*)d_in[12];
    const float* w_noise    = (const float*)d_in[13];
    const float* b_noise    = (const float*)d_in[14];
    const float* temp       = (const float*)d_in[15];
    const float* deep_w1    = (const float*)d_in[16];
    const float* deep_b1    = (const float*)d_in[17];
    const float* deep_w2    = (const float*)d_in[18];
    const float* deep_b2    = (const float*)d_in[19];
    const float* deep_w3    = (const float*)d_in[20];
    const float* deep_b3    = (const float*)d_in[21];
    const float* deep_ln_g  = (const float*)d_in[22];
    const float* deep_ln_b  = (const float*)d_in[23];
    const float* simple_w1  = (const float*)d_in[24];
    const float* simple_b1  = (const float*)d_in[25];
    const float* simple_w2  = (const float*)d_in[26];
    const float* simple_b2  = (const float*)d_in[27];
    const float* simple_ln_g= (const float*)d_in[28];
    const float* simple_ln_b= (const float*)d_in[29];
    float* out = (float*)d_out;

    float *ph, *pq, *pk, *pv, *po, *px1, *ph2, *pa1, *pa2, *py;
    int *pcnt, *ptok;
    cudaGetSymbolAddress((void**)&ph,  g_h);
    cudaGetSymbolAddress((void**)&pq,  g_q);
    cudaGetSymbolAddress((void**)&pk,  g_k);
    cudaGetSymbolAddress((void**)&pv,  g_v);
    cudaGetSymbolAddress((void**)&po,  g_o);
    cudaGetSymbolAddress((void**)&px1, g_x1);
    cudaGetSymbolAddress((void**)&ph2, g_h2);
    cudaGetSymbolAddress((void**)&pa1, g_a1);
    cudaGetSymbolAddress((void**)&pa2, g_a2);
    cudaGetSymbolAddress((void**)&py,  g_y);
    cudaGetSymbolAddress((void**)&pcnt, g_cnt);
    cudaGetSymbolAddress((void**)&ptok, g_tok);

    // opt-in to >48KB dynamic smem (host-side attribute set; not a stream op)
    cudaFuncSetAttribute(tf32_gemm<0>, cudaFuncAttributeMaxDynamicSharedMemorySize, TF32_SMEM);
    cudaFuncSetAttribute(tf32_gemm<1>, cudaFuncAttributeMaxDynamicSharedMemorySize, TF32_SMEM);

    // 1) LN1
    ln_kernel<<<N_, 256>>>(x, ln1_g, ln1_b, ph);

    // 2) QKV (fp32 — feeds router path, keep exact)
    {
        dim3 grid(1, N_/128, H_);
        sgemm_k<128,64,16,8,4,0><<<grid, 256>>>(ph, C_, nullptr,
            wq, HS_, (size_t)C_*HS_, nullptr, nullptr,
            pq, HS_, (size_t)N_*HS_, N_, nullptr, HS_, C_);
        sgemm_k<128,64,16,8,4,0><<<grid, 256>>>(ph, C_, nullptr,
            wk, HS_, (size_t)C_*HS_, nullptr, nullptr,
            pk, HS_, (size_t)N_*HS_, N_, nullptr, HS_, C_);
        sgemm_k<128,64,16,8,4,0><<<grid, 256>>>(ph, C_, nullptr,
            wv, HS_, (size_t)C_*HS_, nullptr, nullptr,
            pv, HS_, (size_t)N_*HS_, N_, nullptr, HS_, C_);
    }

    // 3) causal flash attention (fp32)
    flash_kernel<<<dim3(T_/64, B_*H_), 256>>>(pq, pk, pv, po);

    // 4) out proj + residual (fp32 — feeds router path)
    sgemm_k<128,128,16,8,8,2><<<dim3(C_/128, N_/128), 256>>>(po, C_, nullptr,
        w_proj, C_, 0, b_proj, x, px1, C_, 0, N_, nullptr, C_, C_);

    // 5) LN2
    ln_kernel<<<N_, 256>>>(px1, ln2_g, ln2_b, ph2);

    // 6) router (fp32)
    zero_cnt_kernel<<<1, 32>>>();
    router_kernel<<<N_, 256>>>(ph2, w_route, b_route, w_noise, b_noise, temp, rnoise);

    // 7) expert first layer (gathered rows), GELU epilogue — tf32 pipelined
    for (int e = 0; e < E_; e++) {
        const float* W1 = (e < 2) ? deep_w1 + (size_t)e*C_*F_ : simple_w1 + (size_t)(e-2)*C_*F_;
        const float* B1 = (e < 2) ? deep_b1 + (size_t)e*F_    : simple_b1 + (size_t)(e-2)*F_;
        tf32_gemm<1><<<dim3(F_/128, N_/128), 256, TF32_SMEM>>>(
            ph2, C_, ptok + (size_t)e*N_, W1, F_, B1,
            pa1 + (size_t)e*N_*F_, F_, pcnt + e, F_, C_);
    }
    // 8) deep second layer, GELU — tf32 pipelined
    for (int e = 0; e < 2; e++) {
        tf32_gemm<1><<<dim3(F_/128, N_/128), 256, TF32_SMEM>>>(
            pa1 + (size_t)e*N_*F_, F_, nullptr, deep_w2 + (size_t)e*F_*F_, F_,
            deep_b2 + (size_t)e*F_,
            pa2 + (size_t)e*N_*F_, F_, pcnt + e, F_, F_);
    }
    // 9) expert output layer -> y — tf32 pipelined
    for (int e = 0; e < E_; e++) {
        const float *W, *Bb, *Ain;
        if (e < 2) { W = deep_w3 + (size_t)e*F_*C_;       Bb = deep_b3 + (size_t)e*C_;
                     Ain = pa2 + (size_t)e*N_*F_; }
        else       { W = simple_w2 + (size_t)(e-2)*F_*C_; Bb = simple_b2 + (size_t)(e-2)*C_;
                     Ain = pa1 + (size_t)e*N_*F_; }
        tf32_gemm<0><<<dim3(C_/128, N_/128), 256, TF32_SMEM>>>(
            Ain, F_, nullptr, W, C_, Bb,
            py + (size_t)e*N_*C_, C_, pcnt + e, C_, F_);
    }

    // 10) per-token gated residual-LN combine
    final_kernel<<<N_, 256>>>(px1, ph2, deep_ln_g, deep_ln_b, simple_ln_g, simple_ln_b, out);
}

// round 15
// speedup vs baseline: 2.9013x; 1.2363x over previous
#include <cuda_runtime.h>
#include <cuda_fp16.h>
#include <math.h>
#include <stdint.h>

#define B_   8
#define T_   1024
#define C_   768
#define H_   12
#define E_   8
#define HS_  64
#define F_   3072
#define N_   (B_*T_)
#define LN_EPS 1e-5f
#define ATT_SCALE 0.03608439182435161f

// ---------------- scratch ----------------
__device__ float  g_h  [N_*C_];
__device__ float  g_q  [H_*N_*HS_];
__device__ float  g_k  [H_*N_*HS_];
__device__ float  g_v  [H_*N_*HS_];
__device__ float  g_o  [N_*C_];
__device__ float  g_x1 [N_*C_];
__device__ float  g_h2 [N_*C_];
__device__ __half g_h2f[N_*C_];
__device__ int    g_cnt[E_];
__device__ int    g_tok[E_*N_];
__device__ int    g_texp [N_*2];
__device__ int    g_tslot[N_*2];
__device__ float  g_tgate[N_*2];
__device__ __half g_a1f[(size_t)E_*N_*F_];
__device__ __half g_a2f[(size_t)2 *N_*F_];
__device__ float  g_y  [(size_t)E_*N_*C_];
__device__ __half g_wtAh[(size_t)E_*F_*C_];   // layer1 B^T fp16: [e][F][C]
__device__ __half g_wtBh[(size_t)2 *F_*F_];   // layer2 B^T fp16: [e][F][F]
__device__ __half g_wtCh[(size_t)E_*C_*F_];   // layer3 B^T fp16: [e][C][F]
__device__ float  g_bias1[E_*F_];
__device__ float  g_bias3[E_*C_];

__device__ __forceinline__ float gelu_f(float x) {
    return 0.5f * x * (1.0f + erff(x * 0.7071067811865476f));
}
__device__ __forceinline__ float block_reduce_sum(float v, float* red) {
    int tid = threadIdx.x;
    red[tid] = v; __syncthreads();
    #pragma unroll
    for (int o = 128; o > 0; o >>= 1) {
        if (tid < o) red[tid] += red[tid + o];
        __syncthreads();
    }
    float r = red[0]; __syncthreads(); return r;
}

// ---------------- fp16 mma helpers ----------------
__device__ __forceinline__ void mma_f16(float* c, const uint32_t* a, const uint32_t* b) {
    asm volatile("mma.sync.aligned.m16n8k16.row.col.f32.f16.f16.f32 "
        "{%0,%1,%2,%3}, {%4,%5,%6,%7}, {%8,%9}, {%0,%1,%2,%3};"
        : "+f"(c[0]), "+f"(c[1]), "+f"(c[2]), "+f"(c[3])
        : "r"(a[0]), "r"(a[1]), "r"(a[2]), "r"(a[3]), "r"(b[0]), "r"(b[1]));
}
__device__ __forceinline__ void ldsm_x4(uint32_t* r, uint32_t addr) {
    asm volatile("ldmatrix.sync.aligned.m8n8.x4.shared.b16 {%0,%1,%2,%3}, [%4];"
        : "=r"(r[0]), "=r"(r[1]), "=r"(r[2]), "=r"(r[3]) : "r"(addr));
}
__device__ __forceinline__ void store2(__half* p, float v0, float v1) {
    *(__half2*)p = __floats2half2_rn(v0, v1);
}
__device__ __forceinline__ void store2(float* p, float v0, float v1) {
    *(float2*)p = make_float2(v0, v1);
}

// ---------------- fp16 tensor-core expert GEMM ----------------
// C[M,N] = A[M,K] @ Bt^T + bias.  A,Bt fp16 (Bt: [N][K] row-major), acc fp32.
// EPI: 0 plain, 1 gelu. OutT: __half or float. grid.z = expert, dyn M = cnts[z].
// 128x128 CTA tile, BK=64 halves/stage, 3-stage cp.async, ldmatrix A frags.
#define H_LDA 72                   // halves per smem row (144B, conflict-free)
#define H_STG 36864                // bytes/stage: (128+128) rows * 144B
#define H_SMEM (3 * H_STG)

template<int EPI, typename OutT>
__global__ void __launch_bounds__(256, 2)
h16_gemm(const __half* __restrict__ Adeep, const __half* __restrict__ Asimple,
         size_t aStride, int lda,
         const int* __restrict__ gatherBase, int gatherStride,
         const __half* __restrict__ BtBase, size_t bStride,
         const float* __restrict__ biasBase, int biasStride,
         OutT* __restrict__ CmBase, size_t cStride, int ldc,
         const int* __restrict__ cnts, int K)
{
    extern __shared__ __half hsm[];
    __shared__ int ridx[128];

    const int z = blockIdx.z;
    const int M = cnts[z];
    const int m0 = blockIdx.y * 128;
    if (m0 >= M) return;
    const int n0 = blockIdx.x * 128;

    const __half* Aexp = ((z < 2) ? Adeep : Asimple) + (size_t)z * aStride;
    const __half* Bt   = BtBase + (size_t)z * bStride;

    const int tid = threadIdx.x, lane = tid & 31, wid = tid >> 5;
    const int wm = (wid & 1) * 64, wn = (wid >> 1) * 32;
    const int lr = lane >> 2, lc = lane & 3;

    if (tid < 128) {
        const int* gat = gatherBase ? (gatherBase + (size_t)z * gatherStride) : nullptr;
        int r = m0 + tid;
        ridx[tid] = (r < M) ? (gat ? gat[r] : r) : -1;
    }
    __syncthreads();

    uint32_t sbase = (uint32_t)__cvta_generic_to_shared(hsm);

    // ldmatrix A-frag addresses: m16k16 tile = 4 8x8 matrices
    int grp = lane >> 3, lrw = lane & 7;
    uint32_t a_off[4];
    #pragma unroll
    for (int mt = 0; mt < 4; mt++)
        a_off[mt] = (uint32_t)(((wm + mt*16 + (grp & 1)*8 + lrw) * H_LDA
                               + (grp >> 1) * 8) * 2);

    auto load_stage = [&](int j, int slot) {
        uint32_t stb = sbase + (uint32_t)slot * H_STG;
        const int k0 = j << 6;
        #pragma unroll
        for (int i = 0; i < 4; i++) {            // A: 128 rows x 64 halves
            int idx = tid + (i << 8);
            int row = idx >> 3, c16 = idx & 7;
            uint32_t dst = stb + (uint32_t)(row * 144 + c16 * 16);
            int gr = ridx[row];
            const __half* src = Aexp + (size_t)(gr < 0 ? 0 : gr) * lda + k0 + c16 * 8;
            int sz = (gr >= 0) ? 16 : 0;
            asm volatile("cp.async.cg.shared.global [%0], [%1], 16, %2;"
                         :: "r"(dst), "l"(src), "r"(sz));
        }
        #pragma unroll
        for (int i = 0; i < 4; i++) {            // B: 128 rows x 64 halves
            int idx = tid + (i << 8);
            int row = idx >> 3, c16 = idx & 7;
            uint32_t dst = stb + 18432u + (uint32_t)(row * 144 + c16 * 16);
            const __half* src = Bt + (size_t)(n0 + row) * K + k0 + c16 * 8;
            asm volatile("cp.async.cg.shared.global [%0], [%1], 16;"
                         :: "r"(dst), "l"(src));
        }
    };

    const int iters = K >> 6;
    load_stage(0, 0);
    asm volatile("cp.async.commit_group;" ::: "memory");
    if (iters > 1) load_stage(1, 1);
    asm volatile("cp.async.commit_group;" ::: "memory");

    float acc[4][4][4];
    #pragma unroll
    for (int mt = 0; mt < 4; mt++)
        #pragma unroll
        for (int nt = 0; nt < 4; nt++)
            #pragma unroll
            for (int i = 0; i < 4; i++) acc[mt][nt][i] = 0.f;

    int st = 0;
    for (int it = 0; it < iters; it++) {
        asm volatile("cp.async.wait_group 1;" ::: "memory");
        __syncthreads();
        if (it + 2 < iters) {
            int ps = (st + 2 >= 3) ? st - 1 : st + 2;
            load_stage(it + 2, ps);
        }
        asm volatile("cp.async.commit_group;" ::: "memory");

        uint32_t As_b = sbase + (uint32_t)st * H_STG;
        const __half* Bs = hsm + (size_t)st * (H_STG / 2) + 9216;
        #pragma unroll
        for (int ks = 0; ks < 4; ks++) {          // 4 x k16 per stage
            uint32_t a[4][4], b[4][2];
            #pragma unroll
            for (int mt = 0; mt < 4; mt++)
                ldsm_x4(a[mt], As_b + a_off[mt] + (uint32_t)ks * 32u);
            #pragma unroll
            for (int nt = 0; nt < 4; nt++) {
                const __half* bp = Bs + (wn + nt*8 + lr) * H_LDA + ks*16 + 2*lc;
                b[nt][0] = *(const uint32_t*)bp;
                b[nt][1] = *(const uint32_t*)(bp + 8);
            }
            #pragma unroll
            for (int mt = 0; mt < 4; mt++)
                #pragma unroll
                for (int nt = 0; nt < 4; nt++)
                    mma_f16(acc[mt][nt], a[mt], b[nt]);
        }
        st = (st + 1 >= 3) ? 0 : st + 1;
    }

    // epilogue
    const float* bias = biasBase + (size_t)z * biasStride;
    OutT* Cm = CmBase + (size_t)z * cStride;
    #pragma unroll
    for (int mt = 0; mt < 4; mt++) {
        int r0 = m0 + wm + mt*16 + lr;
        int r1 = r0 + 8;
        #pragma unroll
        for (int nt = 0; nt < 4; nt++) {
            int c = n0 + wn + nt*8 + lc*2;
            float bz0 = bias[c], bz1 = bias[c+1];
            float v0 = acc[mt][nt][0] + bz0, v1 = acc[mt][nt][1] + bz1;
            float v2 = acc[mt][nt][2] + bz0, v3 = acc[mt][nt][3] + bz1;
            if (EPI == 1) { v0 = gelu_f(v0); v1 = gelu_f(v1); v2 = gelu_f(v2); v3 = gelu_f(v3); }
            if (r0 < M) store2(Cm + (size_t)r0*ldc + c, v0, v1);
            if (r1 < M) store2(Cm + (size_t)r1*ldc + c, v2, v3);
        }
    }
}

// ---------------- weight transpose+convert: fp32 in[z][K][Nn] -> fp16 out[z][Nn][K] ----------------
__global__ void transpose_h(const float* __restrict__ in, __half* __restrict__ out,
                            int K, int Nn) {
    __shared__ float t[32][33];
    size_t zo = (size_t)blockIdx.z * (size_t)K * Nn;
    in += zo; out += zo;
    int n0 = blockIdx.x * 32, k0 = blockIdx.y * 32;
    int tx = threadIdx.x, ty = threadIdx.y;   // 32 x 8
    #pragma unroll
    for (int i = 0; i < 4; i++)
        t[ty + 8*i][tx] = in[(size_t)(k0 + ty + 8*i) * Nn + n0 + tx];
    __syncthreads();
    #pragma unroll
    for (int i = 0; i < 4; i++)
        out[(size_t)(n0 + ty + 8*i) * K + k0 + tx] = __float2half(t[tx][ty + 8*i]);
}

__global__ void pack_bias(const float* __restrict__ db1, const float* __restrict__ sb1,
                          const float* __restrict__ db3, const float* __restrict__ sb2,
                          float* __restrict__ o1, float* __restrict__ o3) {
    int i = blockIdx.x * 256 + threadIdx.x;
    if (i < E_ * F_) {
        int e = i / F_, c = i % F_;
        o1[i] = (e < 2) ? db1[e * F_ + c] : sb1[(e - 2) * F_ + c];
    }
    if (i < E_ * C_) {
        int e = i / C_, c = i % C_;
        o3[i] = (e < 2) ? db3[e * C_ + c] : sb2[(e - 2) * C_ + c];
    }
}

// ---------------- LayerNorm (fp32 out; DUAL also writes fp16 copy) ----------------
template<int DUAL>
__global__ void ln_kernel(const float* __restrict__ in, const float* __restrict__ g,
                          const float* __restrict__ b, float* __restrict__ out,
                          __half* __restrict__ outh) {
    __shared__ float red[256];
    int row = blockIdx.x, tid = threadIdx.x;
    const float* x = in + (size_t)row * C_;
    float v0 = x[tid], v1 = x[tid + 256], v2 = x[tid + 512];
    float mean = block_reduce_sum(v0 + v1 + v2, red) * (1.0f / C_);
    float d0 = v0 - mean, d1 = v1 - mean, d2 = v2 - mean;
    float var = block_reduce_sum(d0*d0 + d1*d1 + d2*d2, red) * (1.0f / C_);
    float rs = 1.0f / sqrtf(var + LN_EPS);
    float* y = out + (size_t)row * C_;
    float y0 = d0 * rs * g[tid]       + b[tid];
    float y1 = d1 * rs * g[tid + 256] + b[tid + 256];
    float y2 = d2 * rs * g[tid + 512] + b[tid + 512];
    y[tid] = y0; y[tid + 256] = y1; y[tid + 512] = y2;
    if (DUAL) {
        __half* yh = outh + (size_t)row * C_;
        yh[tid] = __float2half(y0);
        yh[tid + 256] = __float2half(y1);
        yh[tid + 512] = __float2half(y2);
    }
}

// ---------------- generic fp32 SGEMM (attention path) ----------------
template<int BM, int BN, int BK, int TM, int TN, int EPI>
__global__ void sgemm_k(const float* __restrict__ A, int lda,
                        const float* __restrict__ Bm, int ldb, size_t bzs,
                        const float* __restrict__ bias,
                        const float* __restrict__ res,
                        float* __restrict__ Cm, int ldc, size_t czs,
                        int M, int N, int K) {
    constexpr int THREADS = (BM/TM) * (BN/TN);
    int m0 = blockIdx.y * BM;
    int n0 = blockIdx.x * BN;
    Bm += (size_t)blockIdx.z * bzs;
    Cm += (size_t)blockIdx.z * czs;

    __shared__ float As[BK][BM + 4];
    __shared__ float Bs[BK][BN];

    int tid = threadIdx.x;
    int tx = tid % (BN/TN), ty = tid / (BN/TN);
    float acc[TM][TN] = {};
    constexpr int LA4 = (BM*BK) / (THREADS*4);
    constexpr int LB4 = (BK*BN) / (THREADS*4);

    for (int k0 = 0; k0 < K; k0 += BK) {
        #pragma unroll
        for (int i = 0; i < LA4; i++) {
            int idx = (tid + i*THREADS) * 4;
            int ar = idx / BK, ac = idx % BK;
            float4 v = *(const float4*)(A + (size_t)(m0+ar)*lda + k0 + ac);
            As[ac+0][ar] = v.x; As[ac+1][ar] = v.y;
            As[ac+2][ar] = v.z; As[ac+3][ar] = v.w;
        }
        #pragma unroll
        for (int i = 0; i < LB4; i++) {
            int idx = (tid + i*THREADS) * 4;
            int br = idx / BN, bc = idx % BN;
            *(float4*)&Bs[br][bc] = *(const float4*)(Bm + (size_t)(k0+br)*ldb + n0 + bc);
        }
        __syncthreads();
        #pragma unroll
        for (int kk = 0; kk < BK; kk++) {
            float ra[TM], rb[TN];
            #pragma unroll
            for (int i = 0; i < TM; i++) ra[i] = As[kk][ty*TM + i];
            #pragma unroll
            for (int j = 0; j < TN; j++) rb[j] = Bs[kk][tx*TN + j];
            #pragma unroll
            for (int i = 0; i < TM; i++)
                #pragma unroll
                for (int j = 0; j < TN; j++)
                    acc[i][j] += ra[i] * rb[j];
        }
        __syncthreads();
    }
    #pragma unroll
    for (int i = 0; i < TM; i++) {
        int r = m0 + ty*TM + i;
        #pragma unroll
        for (int j = 0; j < TN; j++) {
            int c = n0 + tx*TN + j;
            float v = acc[i][j];
            if (bias) v += bias[c];
            if (EPI == 2) v += res[(size_t)r*ldc + c];
            Cm[(size_t)r*ldc + c] = v;
        }
    }
}

// ---------------- flash attention (fp32, causal) ----------------
__global__ void flash_kernel(const float* __restrict__ Q, const float* __restrict__ Kg,
                             const float* __restrict__ Vg, float* __restrict__ O) {
    constexpr int BQ = 64, BKV = 32;
    int qi = blockIdx.x;
    int bh = blockIdx.y;
    int b = bh / H_, h = bh % H_;
    const float* Qb = Q  + ((size_t)h*N_ + (size_t)b*T_) * HS_;
    const float* Kb = Kg + ((size_t)h*N_ + (size_t)b*T_) * HS_;
    const float* Vb = Vg + ((size_t)h*N_ + (size_t)b*T_) * HS_;

    __shared__ float Qs[BQ][HS_+4];
    __shared__ float Ks[BKV][HS_+4];
    __shared__ float Vs[BKV][HS_+4];
    __shared__ float Ps[BQ][BKV+4];
    __shared__ float mrow[BQ], lrow[BQ];
    __shared__ float redm[BQ][4], reds[BQ][4];

    int tid = threadIdx.x;
    for (int i = tid; i < BQ*HS_/4; i += 256) {
        int idx = i * 4; int r = idx / HS_, c = idx % HS_;
        float4 v = *(const float4*)(Qb + (size_t)(qi*BQ + r)*HS_ + c);
        Qs[r][c+0] = v.x * ATT_SCALE; Qs[r][c+1] = v.y * ATT_SCALE;
        Qs[r][c+2] = v.z * ATT_SCALE; Qs[r][c+3] = v.w * ATT_SCALE;
    }
    if (tid < BQ) { mrow[tid] = -INFINITY; lrow[tid] = 0.f; }

    int r = tid / 4, cg = tid % 4;
    int rg = qi*BQ + r;
    float Oacc[16];
    #pragma unroll
    for (int i = 0; i < 16; i++) Oacc[i] = 0.f;

    int jmax = 2*qi + 1;
    for (int j = 0; j <= jmax; j++) {
        __syncthreads();
        for (int i = tid; i < BKV*HS_/4; i += 256) {
            int idx = i * 4; int rr = idx / HS_, c = idx % HS_;
            float4 kv = *(const float4*)(Kb + (size_t)(j*BKV + rr)*HS_ + c);
            Ks[rr][c+0] = kv.x; Ks[rr][c+1] = kv.y; Ks[rr][c+2] = kv.z; Ks[rr][c+3] = kv.w;
            float4 vv = *(const float4*)(Vb + (size_t)(j*BKV + rr)*HS_ + c);
            Vs[rr][c+0] = vv.x; Vs[rr][c+1] = vv.y; Vs[rr][c+2] = vv.z; Vs[rr][c+3] = vv.w;
        }
        __syncthreads();

        float s[8];
        #pragma unroll
        for (int i = 0; i < 8; i++) s[i] = 0.f;
        #pragma unroll
        for (int d0 = 0; d0 < HS_; d0 += 16) {
            float qreg[16];
            #pragma unroll
            for (int d = 0; d < 16; d++) qreg[d] = Qs[r][d0+d];
            #pragma unroll
            for (int i = 0; i < 8; i++) {
                int c = cg*8 + i;
                #pragma unroll
                for (int d = 0; d < 16; d++)
                    s[i] += qreg[d] * Ks[c][d0+d];
            }
        }
        float lm = -INFINITY;
        #pragma unroll
        for (int i = 0; i < 8; i++) {
            int cgl = j*BKV + cg*8 + i;
            if (cgl > rg) s[i] = -INFINITY;
            lm = fmaxf(lm, s[i]);
        }
        redm[r][cg] = lm;
        __syncthreads();
        float mprev = mrow[r];
        float mnew = fmaxf(fmaxf(redm[r][0], redm[r][1]), fmaxf(redm[r][2], redm[r][3]));
        mnew = fmaxf(mprev, mnew);
        float ls = 0.f;
        #pragma unroll
        for (int i = 0; i < 8; i++) {
            float p = expf(s[i] - mnew);
            Ps[r][cg*8 + i] = p;
            ls += p;
        }
        reds[r][cg] = ls;
        float alpha = expf(mprev - mnew);
        __syncthreads();
        if (cg == 0) {
            float totl = reds[r][0] + reds[r][1] + reds[r][2] + reds[r][3];
            lrow[r] = lrow[r] * alpha + totl;
            mrow[r] = mnew;
        }
        #pragma unroll
        for (int d = 0; d < 16; d++) Oacc[d] *= alpha;
        #pragma unroll
        for (int c = 0; c < BKV; c++) {
            float p = Ps[r][c];
            #pragma unroll
            for (int d = 0; d < 16; d++)
                Oacc[d] += p * Vs[c][cg*16 + d];
        }
    }
    __syncthreads();
    float inv = 1.0f / lrow[r];
    float* orow = O + (size_t)(b*T_ + qi*BQ + r) * C_ + h*HS_ + cg*16;
    #pragma unroll
    for (int d = 0; d < 16; d++) orow[d] = Oacc[d] * inv;
}

// ---------------- router ----------------
__global__ void zero_cnt_kernel() {
    if (threadIdx.x < E_) g_cnt[threadIdx.x] = 0;
}
__global__ void router_kernel(const float* __restrict__ h2,
                              const float* __restrict__ w_route, const float* __restrict__ b_route,
                              const float* __restrict__ w_noise, const float* __restrict__ b_noise,
                              const float* __restrict__ temp_p, const float* __restrict__ rnoise) {
    int n = blockIdx.x, tid = threadIdx.x;
    __shared__ float hrow[C_];
    __shared__ float sums[16];
    for (int i = tid; i < C_; i += 256) hrow[i] = h2[(size_t)n*C_ + i];
    __syncthreads();
    int w = tid / 32, lane = tid % 32;
    float sr = 0.f, sn = 0.f;
    for (int c = lane; c < C_; c += 32) {
        float hv = hrow[c];
        sr += hv * w_route[c*E_ + w];
        sn += hv * w_noise[c*E_ + w];
    }
    #pragma unroll
    for (int o = 16; o > 0; o >>= 1) {
        sr += __shfl_down_sync(0xffffffffu, sr, o);
        sn += __shfl_down_sync(0xffffffffu, sn, o);
    }
    if (lane == 0) { sums[w] = sr; sums[8 + w] = sn; }
    __syncthreads();
    if (tid == 0) {
        float temp = fminf(fmaxf(temp_p[0], 0.5f), 2.0f);
        float noisy[E_];
        #pragma unroll
        for (int e = 0; e < E_; e++) {
            float logit = sums[e] + b_route[e];
            float z = sums[8 + e] + b_noise[e];
            float sp = (z > 20.f) ? z : log1pf(expf(z));
            noisy[e] = logit + temp * rnoise[(size_t)n*E_ + e] * sp;
        }
        int i0 = 0; float v0 = noisy[0];
        #pragma unroll
        for (int e = 1; e < E_; e++) if (noisy[e] > v0) { v0 = noisy[e]; i0 = e; }
        int i1 = -1; float v1 = -INFINITY;
        #pragma unroll
        for (int e = 0; e < E_; e++) if (e != i0 && noisy[e] > v1) { v1 = noisy[e]; i1 = e; }
        float eb = expf(v1 - v0);
        float gg0 = 1.0f / (1.0f + eb);
        float gg1 = eb / (1.0f + eb);
        int s0 = atomicAdd(&g_cnt[i0], 1);
        int s1 = atomicAdd(&g_cnt[i1], 1);
        g_tok[i0*N_ + s0] = n;  g_tok[i1*N_ + s1] = n;
        g_texp [n*2] = i0;      g_texp [n*2+1] = i1;
        g_tslot[n*2] = s0;      g_tslot[n*2+1] = s1;
        g_tgate[n*2] = gg0;     g_tgate[n*2+1] = gg1;
    }
}

// ---------------- final combine ----------------
__global__ void final_kernel(const float* __restrict__ x1, const float* __restrict__ h2,
                             const float* __restrict__ dlg, const float* __restrict__ dlb,
                             const float* __restrict__ slg, const float* __restrict__ slb,
                             float* __restrict__ out) {
    __shared__ float red[256];
    int n = blockIdx.x, tid = threadIdx.x;
    const float* hr = h2 + (size_t)n*C_;
    float h0 = hr[tid], h1 = hr[tid+256], h2v = hr[tid+512];
    float a0 = 0.f, a1 = 0.f, a2 = 0.f;
    for (int jj = 0; jj < 2; jj++) {
        int e = g_texp[n*2 + jj];
        int s = g_tslot[n*2 + jj];
        float gt = g_tgate[n*2 + jj];
        const float* y = g_y + ((size_t)e*N_ + s) * C_;
        float z0 = h0 + y[tid], z1 = h1 + y[tid+256], z2 = h2v + y[tid+512];
        float mean = block_reduce_sum(z0 + z1 + z2, red) * (1.0f / C_);
        float d0 = z0 - mean, d1 = z1 - mean, d2 = z2 - mean;
        float var = block_reduce_sum(d0*d0 + d1*d1 + d2*d2, red) * (1.0f / C_);
        float rs = 1.0f / sqrtf(var + LN_EPS);
        const float* gam; const float* bet;
        if (e < 2) { gam = dlg + e*C_;       bet = dlb + e*C_; }
        else       { gam = slg + (e-2)*C_;   bet = slb + (e-2)*C_; }
        a0 += gt * (d0*rs*gam[tid]     + bet[tid]);
        a1 += gt * (d1*rs*gam[tid+256] + bet[tid+256]);
        a2 += gt * (d2*rs*gam[tid+512] + bet[tid+512]);
    }
    const float* xr = x1 + (size_t)n*C_;
    float* orow = out + (size_t)n*C_;
    orow[tid]     = xr[tid]     + a0;
    orow[tid+256] = xr[tid+256] + a1;
    orow[tid+512] = xr[tid+512] + a2;
}

// ---------------- host ----------------
extern "C" void kernel_launch(void* const* d_in, const int* in_sizes, int n_in,
                              void* d_out, int out_size) {
    const float* x          = (const float*)d_in[0];
    const float* rnoise     = (const float*)d_in[1];
    const float* wq         = (const float*)d_in[2];
    const float* wk         = (const float*)d_in[3];
    const float* wv         = (const float*)d_in[4];
    const float* w_proj     = (const float*)d_in[5];
    const float* b_proj     = (const float*)d_in[6];
    const float* ln1_g      = (const float*)d_in[7];
    const float* ln1_b      = (const float*)d_in[8];
    const float* ln2_g      = (const float*)d_in[9];
    const float* ln2_b      = (const float*)d_in[10];
    const float* w_route    = (const float*)d_in[11];
    const float* b_route    = (const float*)d_in[12];
    const float* w_noise    = (const float*)d_in[13];
    const float* b_noise    = (const float*)d_in[14];
    const float* temp       = (const float*)d_in[15];
    const float* deep_w1    = (const float*)d_in[16];
    const float* deep_b1    = (const float*)d_in[17];
    const float* deep_w2    = (const float*)d_in[18];
    const float* deep_b2    = (const float*)d_in[19];
    const float* deep_w3    = (const float*)d_in[20];
    const float* deep_b3    = (const float*)d_in[21];
    const float* deep_ln_g  = (const float*)d_in[22];
    const float* deep_ln_b  = (const float*)d_in[23];
    const float* simple_w1  = (const float*)d_in[24];
    const float* simple_b1  = (const float*)d_in[25];
    const float* simple_w2  = (const float*)d_in[26];
    const float* simple_b2  = (const float*)d_in[27];
    const float* simple_ln_g= (const float*)d_in[28];
    const float* simple_ln_b= (const float*)d_in[29];
    float* out = (float*)d_out;

    float *ph, *pq, *pk, *pv, *po, *px1, *ph2, *py, *pb1, *pb3;
    __half *ph2f, *pa1f, *pa2f, *pwtAh, *pwtBh, *pwtCh;
    int *pcnt, *ptok;
    cudaGetSymbolAddress((void**)&ph,   g_h);
    cudaGetSymbolAddress((void**)&pq,   g_q);
    cudaGetSymbolAddress((void**)&pk,   g_k);
    cudaGetSymbolAddress((void**)&pv,   g_v);
    cudaGetSymbolAddress((void**)&po,   g_o);
    cudaGetSymbolAddress((void**)&px1,  g_x1);
    cudaGetSymbolAddress((void**)&ph2,  g_h2);
    cudaGetSymbolAddress((void**)&ph2f, g_h2f);
    cudaGetSymbolAddress((void**)&pa1f, g_a1f);
    cudaGetSymbolAddress((void**)&pa2f, g_a2f);
    cudaGetSymbolAddress((void**)&py,   g_y);
    cudaGetSymbolAddress((void**)&pwtAh, g_wtAh);
    cudaGetSymbolAddress((void**)&pwtBh, g_wtBh);
    cudaGetSymbolAddress((void**)&pwtCh, g_wtCh);
    cudaGetSymbolAddress((void**)&pb1,  g_bias1);
    cudaGetSymbolAddress((void**)&pb3,  g_bias3);
    cudaGetSymbolAddress((void**)&pcnt, g_cnt);
    cudaGetSymbolAddress((void**)&ptok, g_tok);

    cudaFuncSetAttribute(h16_gemm<1,__half>, cudaFuncAttributeMaxDynamicSharedMemorySize, H_SMEM);
    cudaFuncSetAttribute(h16_gemm<0,float>,  cudaFuncAttributeMaxDynamicSharedMemorySize, H_SMEM);

    // 0) weight transpose+fp16 convert, bias packing
    {
        dim3 th(32, 8);
        transpose_h<<<dim3(F_/32, C_/32, 2), th>>>(deep_w1,   pwtAh,                   C_, F_);
        transpose_h<<<dim3(F_/32, C_/32, 6), th>>>(simple_w1, pwtAh + (size_t)2*F_*C_, C_, F_);
        transpose_h<<<dim3(F_/32, F_/32, 2), th>>>(deep_w2,   pwtBh,                   F_, F_);
        transpose_h<<<dim3(C_/32, F_/32, 2), th>>>(deep_w3,   pwtCh,                   F_, C_);
        transpose_h<<<dim3(C_/32, F_/32, 6), th>>>(simple_w2, pwtCh + (size_t)2*C_*F_, F_, C_);
        pack_bias<<<(E_*F_ + 255)/256, 256>>>(deep_b1, simple_b1, deep_b3, simple_b2, pb1, pb3);
    }

    // 1) LN1 (fp32 only)
    ln_kernel<0><<<N_, 256>>>(x, ln1_g, ln1_b, ph, nullptr);

    // 2) QKV (fp32 — router path stays exact)
    {
        dim3 grid(1, N_/128, H_);
        sgemm_k<128,64,16,8,4,0><<<grid, 256>>>(ph, C_, wq, HS_, (size_t)C_*HS_,
            nullptr, nullptr, pq, HS_, (size_t)N_*HS_, N_, HS_, C_);
        sgemm_k<128,64,16,8,4,0><<<grid, 256>>>(ph, C_, wk, HS_, (size_t)C_*HS_,
            nullptr, nullptr, pk, HS_, (size_t)N_*HS_, N_, HS_, C_);
        sgemm_k<128,64,16,8,4,0><<<grid, 256>>>(ph, C_, wv, HS_, (size_t)C_*HS_,
            nullptr, nullptr, pv, HS_, (size_t)N_*HS_, N_, HS_, C_);
    }

    // 3) flash attention
    flash_kernel<<<dim3(T_/64, B_*H_), 256>>>(pq, pk, pv, po);

    // 4) out proj + residual
    sgemm_k<128,128,16,8,8,2><<<dim3(C_/128, N_/128), 256>>>(po, C_, w_proj, C_, 0,
        b_proj, x, px1, C_, 0, N_, C_, C_);

    // 5) LN2 (fp32 + fp16 copy for expert GEMMs)
    ln_kernel<1><<<N_, 256>>>(px1, ln2_g, ln2_b, ph2, ph2f);

    // 6) router (fp32)
    zero_cnt_kernel<<<1, 32>>>();
    router_kernel<<<N_, 256>>>(ph2, w_route, b_route, w_noise, b_noise, temp, rnoise);

    // 7) expert layer 1 (gathered, GELU) -> a1 fp16
    h16_gemm<1,__half><<<dim3(F_/128, N_/128, E_), 256, H_SMEM>>>(
        ph2f, ph2f, 0, C_, ptok, N_,
        pwtAh, (size_t)F_*C_, pb1, F_,
        pa1f, (size_t)N_*F_, F_, pcnt, C_);

    // 8) deep layer 2 (GELU) -> a2 fp16
    h16_gemm<1,__half><<<dim3(F_/128, N_/128, 2), 256, H_SMEM>>>(
        pa1f, pa1f, (size_t)N_*F_, F_, nullptr, 0,
        pwtBh, (size_t)F_*F_, deep_b2, F_,
        pa2f, (size_t)N_*F_, F_, pcnt, F_);

    // 9) expert output layer -> y fp32
    h16_gemm<0,float><<<dim3(C_/128, N_/128, E_), 256, H_SMEM>>>(
        pa2f, pa1f, (size_t)N_*F_, F_, nullptr, 0,
        pwtCh, (size_t)C_*F_, pb3, C_,
        py, (size_t)N_*C_, C_, pcnt, F_);

    // 10) gated residual-LN combine
    final_kernel<<<N_, 256>>>(px1, ph2, deep_ln_g, deep_ln_b, simple_ln_g, simple_ln_b, out);
}